// round 3
// baseline (speedup 1.0000x reference)
#include <cuda_runtime.h>
#include <cstdint>
#include <cmath>

// ---------------- problem constants ----------------
constexpr int cB = 128, cT = 128, cE = 1024, cH = 1024, cNH = 8, cA = 64;
constexpr int cKV = cNH * cA;          // 512
constexpr int BE  = cB * cE;           // 131072

// ---------------- persistent device scratch ----------------
__device__ float g_MUS [cT * BE];          // (T,B,E)
__device__ float g_SIGS[cT * BE];          // (T,B,E)
__device__ float g_S   [cT * BE];          // (T,B,E)
__device__ float g_K   [cT * cB * cKV];    // (T,B,512)
__device__ float g_V   [cT * cB * cKV];
__device__ float g_X   [cB * 2048];        // [encs | context]
__device__ float g_H   [cB * cH];
__device__ float g_GI  [cB * 3072];
__device__ float g_GH  [cB * 3072];
__device__ float g_Q   [cB * cKV];
__device__ float g_CTX [cB * cKV];

// ---------------- threefry2x32 (jax-exact) ----------------
__device__ __forceinline__ uint2 tf2x32(unsigned k0, unsigned k1, unsigned x0, unsigned x1) {
    unsigned k2 = k0 ^ k1 ^ 0x1BD11BDAu;
    x0 += k0; x1 += k1;
#define TFR(r) x0 += x1; x1 = __funnelshift_l(x1, x1, r); x1 ^= x0;
    TFR(13) TFR(15) TFR(26) TFR(6)   x0 += k1; x1 += k2 + 1u;
    TFR(17) TFR(29) TFR(16) TFR(24)  x0 += k2; x1 += k0 + 2u;
    TFR(13) TFR(15) TFR(26) TFR(6)   x0 += k0; x1 += k1 + 3u;
    TFR(17) TFR(29) TFR(16) TFR(24)  x0 += k1; x1 += k2 + 4u;
    TFR(13) TFR(15) TFR(26) TFR(6)   x0 += k2; x1 += k0 + 5u;
#undef TFR
    return make_uint2(x0, x1);
}

static inline void tf2x32_host(unsigned k0, unsigned k1, unsigned x0, unsigned x1,
                               unsigned& o0, unsigned& o1) {
    auto rotl = [](unsigned v, int d) { return (v << d) | (v >> (32 - d)); };
    unsigned k2 = k0 ^ k1 ^ 0x1BD11BDAu;
    x0 += k0; x1 += k1;
    const int ra[4] = {13, 15, 26, 6}, rb[4] = {17, 29, 16, 24};
    for (int g = 0; g < 5; g++) {
        const int* R = (g & 1) ? rb : ra;
        for (int r = 0; r < 4; r++) { x0 += x1; x1 = rotl(x1, R[r]); x1 ^= x0; }
        unsigned ks[3] = {k0, k1, k2};
        x0 += ks[(g + 1) % 3];
        x1 += ks[(g + 2) % 3] + (unsigned)(g + 1);
    }
    o0 = x0; o1 = x1;
}

// uniform-bits -> N(0,1): jax _uniform + sqrt(2)*erf_inv (XLA ErfInv32 / Giles)
__device__ __forceinline__ float tf_normal(unsigned bits) {
    float f = __uint_as_float((bits >> 9) | 0x3f800000u) - 1.0f;
    float u = fmaf(f, 2.0f, -0.99999994f);
    u = fmaxf(u, -0.99999994f);
    float w = -log1pf(-u * u);
    float p;
    if (w < 5.0f) {
        w -= 2.5f;
        p = 2.81022636e-08f;
        p = fmaf(p, w, 3.43273939e-07f);
        p = fmaf(p, w, -3.5233877e-06f);
        p = fmaf(p, w, -4.39150654e-06f);
        p = fmaf(p, w, 0.00021858087f);
        p = fmaf(p, w, -0.00125372503f);
        p = fmaf(p, w, -0.00417768164f);
        p = fmaf(p, w, 0.246640727f);
        p = fmaf(p, w, 1.50140941f);
    } else {
        w = sqrtf(w) - 3.0f;
        p = -0.000200214257f;
        p = fmaf(p, w, 0.000100950558f);
        p = fmaf(p, w, 0.00134934322f);
        p = fmaf(p, w, -0.00367342844f);
        p = fmaf(p, w, 0.00573950773f);
        p = fmaf(p, w, -0.0076224613f);
        p = fmaf(p, w, 0.00943887047f);
        p = fmaf(p, w, 1.00167406f);
        p = fmaf(p, w, 2.83297682f);
    }
    return 1.4142135623730951f * (p * u);
}

// partitionable-threefry random bits: per element linear idx, counter (hi=0, lo=idx),
// bits = lane0 ^ lane1
__device__ __forceinline__ float eps_at(unsigned k0, unsigned k1, unsigned idx) {
    uint2 r = tf2x32(k0, k1, 0u, idx);
    return tf_normal(r.x ^ r.y);
}

// ---------------- init: X = [encs | 0], H = 0 ----------------
__global__ void k_init(const float* __restrict__ encs) {
    int idx = blockIdx.x * 256 + threadIdx.x;
    if (idx < cB * 2048) {
        int b = idx >> 11, c = idx & 2047;
        g_X[idx] = (c < cE) ? encs[b * cE + c] : 0.f;
    }
    if (idx < cB * cH) g_H[idx] = 0.f;
}

// ---------------- generic SGEMM ----------------
struct GemmDesc {
    const float* A; const float* Bm; float* C; const float* bias;
    int lda, ldb, ldc, M, K, transB, act;  // act: 0 none, 1 softplus
};
struct GemmBatch { GemmDesc g[3]; };

template <int BM, int BN, int BK, int TM, int TN>
__global__ __launch_bounds__(256) void sgemm_tpl(GemmBatch batch) {
    GemmDesc d = batch.g[blockIdx.z];
    int m0 = blockIdx.x * BM;
    if (m0 >= d.M) return;
    int n0 = blockIdx.y * BN;

    __shared__ __align__(16) float As[BK][BM];
    __shared__ __align__(16) float Bs[BK][BN];

    int tid = threadIdx.x;
    int tx = tid % (BN / TN);
    int ty = tid / (BN / TN);

    float acc[TM][TN];
#pragma unroll
    for (int r = 0; r < TM; r++)
#pragma unroll
        for (int c = 0; c < TN; c++) acc[r][c] = 0.f;

    for (int k0 = 0; k0 < d.K; k0 += BK) {
        {
            int row = tid / (BK / 4);
            int kc = (tid % (BK / 4)) * 4;
            float4 v = *reinterpret_cast<const float4*>(d.A + (size_t)(m0 + row) * d.lda + k0 + kc);
            As[kc + 0][row] = v.x; As[kc + 1][row] = v.y;
            As[kc + 2][row] = v.z; As[kc + 3][row] = v.w;
        }
        if (!d.transB) {
            int kk = tid / (BN / 4);
            int nc = (tid % (BN / 4)) * 4;
            *reinterpret_cast<float4*>(&Bs[kk][nc]) =
                *reinterpret_cast<const float4*>(d.Bm + (size_t)(k0 + kk) * d.ldb + n0 + nc);
        } else {
            int nn = tid / (BK / 4);
            int kc = (tid % (BK / 4)) * 4;
            float4 v = *reinterpret_cast<const float4*>(d.Bm + (size_t)(n0 + nn) * d.ldb + k0 + kc);
            Bs[kc + 0][nn] = v.x; Bs[kc + 1][nn] = v.y;
            Bs[kc + 2][nn] = v.z; Bs[kc + 3][nn] = v.w;
        }
        __syncthreads();
#pragma unroll
        for (int kk = 0; kk < BK; kk++) {
            float af[TM], bf[TN];
#pragma unroll
            for (int u = 0; u < TM / 4; u++) {
                float4 v = *reinterpret_cast<const float4*>(&As[kk][ty * TM + u * 4]);
                af[u * 4 + 0] = v.x; af[u * 4 + 1] = v.y; af[u * 4 + 2] = v.z; af[u * 4 + 3] = v.w;
            }
#pragma unroll
            for (int u = 0; u < TN / 4; u++) {
                float4 v = *reinterpret_cast<const float4*>(&Bs[kk][tx * TN + u * 4]);
                bf[u * 4 + 0] = v.x; bf[u * 4 + 1] = v.y; bf[u * 4 + 2] = v.z; bf[u * 4 + 3] = v.w;
            }
#pragma unroll
            for (int r = 0; r < TM; r++)
#pragma unroll
                for (int c = 0; c < TN; c++) acc[r][c] = fmaf(af[r], bf[c], acc[r][c]);
        }
        __syncthreads();
    }
#pragma unroll
    for (int r = 0; r < TM; r++) {
        int m = m0 + ty * TM + r;
#pragma unroll
        for (int c4 = 0; c4 < TN / 4; c4++) {
            int n = n0 + tx * TN + c4 * 4;
            float4 bv = d.bias ? *reinterpret_cast<const float4*>(d.bias + n)
                               : make_float4(0.f, 0.f, 0.f, 0.f);
            float4 v;
            v.x = acc[r][c4 * 4 + 0] + bv.x;
            v.y = acc[r][c4 * 4 + 1] + bv.y;
            v.z = acc[r][c4 * 4 + 2] + bv.z;
            v.w = acc[r][c4 * 4 + 3] + bv.w;
            if (d.act == 1) {
                v.x = fmaxf(v.x, 0.f) + log1pf(expf(-fabsf(v.x)));
                v.y = fmaxf(v.y, 0.f) + log1pf(expf(-fabsf(v.y)));
                v.z = fmaxf(v.z, 0.f) + log1pf(expf(-fabsf(v.z)));
                v.w = fmaxf(v.w, 0.f) + log1pf(expf(-fabsf(v.w)));
            }
            *reinterpret_cast<float4*>(d.C + (size_t)m * d.ldc + n) = v;
        }
    }
}

// ---------------- GRU gate combine ----------------
__global__ void k_gru_combine(const float* __restrict__ b_ih, const float* __restrict__ b_hh) {
    int idx = blockIdx.x * 256 + threadIdx.x;
    int b = idx >> 10, m = idx & 1023;
    const float* gi = g_GI + b * 3072;
    const float* gh = g_GH + b * 3072;
    float ir = gi[m] + b_ih[m];
    float iz = gi[m + 1024] + b_ih[m + 1024];
    float in = gi[m + 2048] + b_ih[m + 2048];
    float hr = gh[m] + b_hh[m];
    float hz = gh[m + 1024] + b_hh[m + 1024];
    float hn = gh[m + 2048] + b_hh[m + 2048];
    float r = 1.f / (1.f + expf(-(ir + hr)));
    float z = 1.f / (1.f + expf(-(iz + hz)));
    float n = tanhf(fmaf(r, hn, in));
    float h = g_H[idx];
    g_H[idx] = fmaf(z, h - n, n);
}

// ---------------- sample s[j<=i]: grid = (i+1)*128 blocks, one per (j,b) ----
__global__ __launch_bounds__(256) void k_gen_s(unsigned k0, unsigned k1) {
    int b = blockIdx.x & 127;
    int j = blockIdx.x >> 7;
    int e = threadIdx.x << 2;
    size_t off = (size_t)(j * cB + b) * cE + e;
    float4 mu = *reinterpret_cast<const float4*>(g_MUS + off);
    float4 sg = *reinterpret_cast<const float4*>(g_SIGS + off);
    unsigned p = (unsigned)((b * cT + j) * cE + e);  // row-major (B,T,E) linear idx
    float4 s;
    s.x = fmaf(eps_at(k0, k1, p + 0), sg.x, mu.x);
    s.y = fmaf(eps_at(k0, k1, p + 1), sg.y, mu.y);
    s.z = fmaf(eps_at(k0, k1, p + 2), sg.z, mu.z);
    s.w = fmaf(eps_at(k0, k1, p + 3), sg.w, mu.w);
    *reinterpret_cast<float4*>(g_S + off) = s;
}

// ---------------- final output (B,T,E) ----------------
__global__ __launch_bounds__(256) void k_gen_out(float* __restrict__ out, unsigned k0, unsigned k1) {
    int b = blockIdx.x & 127;
    int j = blockIdx.x >> 7;
    int e = threadIdx.x << 2;
    size_t off = (size_t)(j * cB + b) * cE + e;
    float4 mu = *reinterpret_cast<const float4*>(g_MUS + off);
    float4 sg = *reinterpret_cast<const float4*>(g_SIGS + off);
    unsigned p = (unsigned)((b * cT + j) * cE + e);
    float4 s;
    s.x = fmaf(eps_at(k0, k1, p + 0), sg.x, mu.x);
    s.y = fmaf(eps_at(k0, k1, p + 1), sg.y, mu.y);
    s.z = fmaf(eps_at(k0, k1, p + 2), sg.z, mu.z);
    s.w = fmaf(eps_at(k0, k1, p + 3), sg.w, mu.w);
    *reinterpret_cast<float4*>(out + p) = s;   // out linear index == p
}

// ---------------- attention for row i ----------------
__global__ __launch_bounds__(128) void k_attn(int nj) {
    int b = blockIdx.x, hh = blockIdx.y, tid = threadIdx.x;
    __shared__ __align__(16) float qs[cA];
    __shared__ float wsh[128];
    __shared__ float red[4];
    __shared__ float stat[2];
    if (tid < cA) qs[tid] = g_Q[b * cKV + hh * cA + tid];
    __syncthreads();

    float s = -3.0e38f;
    if (tid < nj) {
        const float* kr = g_K + ((size_t)tid * cB + b) * cKV + hh * cA;
        float acc = 0.f;
#pragma unroll
        for (int u = 0; u < 16; u++) {
            float4 kv = reinterpret_cast<const float4*>(kr)[u];
            float4 q4 = reinterpret_cast<const float4*>(qs)[u];
            acc += kv.x * q4.x + kv.y * q4.y + kv.z * q4.z + kv.w * q4.w;
        }
        s = acc * 0.125f;
    }
    float m = s;
#pragma unroll
    for (int o = 16; o; o >>= 1) m = fmaxf(m, __shfl_xor_sync(0xffffffffu, m, o));
    if ((tid & 31) == 0) red[tid >> 5] = m;
    __syncthreads();
    if (tid == 0) stat[0] = fmaxf(fmaxf(red[0], red[1]), fmaxf(red[2], red[3]));
    __syncthreads();
    float mx = stat[0];
    float w = (tid < nj) ? expf(s - mx) : 0.f;
    wsh[tid] = w;
    float sum = w;
#pragma unroll
    for (int o = 16; o; o >>= 1) sum += __shfl_xor_sync(0xffffffffu, sum, o);
    if ((tid & 31) == 0) red[tid >> 5] = sum;
    __syncthreads();
    if (tid == 0) stat[1] = red[0] + red[1] + red[2] + red[3];
    __syncthreads();
    float inv = 1.f / stat[1];
    if (tid < cA) {
        float acc = 0.f;
        for (int j = 0; j < nj; j++)
            acc = fmaf(wsh[j], g_V[((size_t)j * cB + b) * cKV + hh * cA + tid], acc);
        g_CTX[b * cKV + hh * cA + tid] = acc * inv;
    }
}

// ---------------- host side ----------------
static GemmDesc mk(const float* A, int lda, const float* Bm, int ldb, int transB,
                   float* C, int ldc, const float* bias, int M, int K, int act) {
    GemmDesc d;
    d.A = A; d.Bm = Bm; d.C = C; d.bias = bias;
    d.lda = lda; d.ldb = ldb; d.ldc = ldc; d.M = M; d.K = K; d.transB = transB; d.act = act;
    return d;
}

extern "C" void kernel_launch(void* const* d_in, const int* in_sizes, int n_in,
                              void* d_out, int out_size) {
    const float* encs  = (const float*)d_in[0];
    const float* W_ih  = (const float*)d_in[1];
    const float* W_hh  = (const float*)d_in[2];
    const float* b_ih  = (const float*)d_in[3];
    const float* b_hh  = (const float*)d_in[4];
    const float* W_mu  = (const float*)d_in[5];
    const float* b_mu  = (const float*)d_in[6];
    const float* W_sig = (const float*)d_in[7];
    const float* b_sig = (const float*)d_in[8];
    const float* W_q   = (const float*)d_in[9];
    const float* b_q   = (const float*)d_in[10];
    const float* W_k   = (const float*)d_in[11];
    const float* b_k   = (const float*)d_in[12];
    const float* W_v   = (const float*)d_in[13];
    const float* b_v   = (const float*)d_in[14];
    const float* W_o   = (const float*)d_in[15];
    const float* b_o   = (const float*)d_in[16];
    float* out = (float*)d_out;

    // per-step threefry keys: fold_in(key(1234), i) = threefry([0,1234], [0,i])
    unsigned key0[cT], key1[cT];
    for (int i = 0; i < cT; i++) tf2x32_host(0u, 1234u, 0u, (unsigned)i, key0[i], key1[i]);

    float *pMUS, *pSIGS, *pS, *pK, *pV, *pX, *pH, *pGI, *pGH, *pQ, *pCTX;
    cudaGetSymbolAddress((void**)&pMUS, g_MUS);
    cudaGetSymbolAddress((void**)&pSIGS, g_SIGS);
    cudaGetSymbolAddress((void**)&pS, g_S);
    cudaGetSymbolAddress((void**)&pK, g_K);
    cudaGetSymbolAddress((void**)&pV, g_V);
    cudaGetSymbolAddress((void**)&pX, g_X);
    cudaGetSymbolAddress((void**)&pH, g_H);
    cudaGetSymbolAddress((void**)&pGI, g_GI);
    cudaGetSymbolAddress((void**)&pGH, g_GH);
    cudaGetSymbolAddress((void**)&pQ, g_Q);
    cudaGetSymbolAddress((void**)&pCTX, g_CTX);

    k_init<<<1024, 256>>>(encs);

    for (int i = 0; i < cT; i++) {
        GemmBatch gb{};
        gb.g[0] = mk(pX, 2048, W_ih, 2048, 1, pGI, 3072, nullptr, cB, 2048, 0);
        gb.g[1] = mk(pH, 1024, W_hh, 1024, 1, pGH, 3072, nullptr, cB, 1024, 0);
        gb.g[2] = gb.g[1];
        sgemm_tpl<64, 64, 16, 4, 4><<<dim3(2, 48, 2), 256>>>(gb);

        k_gru_combine<<<512, 256>>>(b_ih, b_hh);

        GemmBatch msb{};
        msb.g[0] = mk(pH, 1024, W_mu, 1024, 0, pMUS + (size_t)i * BE, 1024, b_mu, cB, 1024, 0);
        msb.g[1] = mk(pH, 1024, W_sig, 1024, 0, pSIGS + (size_t)i * BE, 1024, b_sig, cB, 1024, 1);
        msb.g[2] = msb.g[0];
        sgemm_tpl<64, 64, 16, 4, 4><<<dim3(2, 16, 2), 256>>>(msb);

        if (i < cT - 1) {  // step 127's attention/context never consumed
            k_gen_s<<<(i + 1) * 128, 256>>>(key0[i], key1[i]);

            GemmBatch kb{};
            kb.g[0] = mk(pS, 1024, W_k, 512, 0, pK, 512, b_k, (i + 1) * cB, 1024, 0);
            kb.g[1] = mk(pS, 1024, W_v, 512, 0, pV, 512, b_v, (i + 1) * cB, 1024, 0);
            kb.g[2] = mk(pS + (size_t)i * BE, 1024, W_q, 512, 0, pQ, 512, b_q, cB, 1024, 0);
            sgemm_tpl<128, 128, 8, 8, 8><<<dim3(i + 1, 4, 3), 256>>>(kb);

            k_attn<<<dim3(128, 8), 128>>>(i + 1);

            GemmBatch ob{};
            ob.g[0] = mk(pCTX, 512, W_o, 1024, 0, pX + 1024, 2048, b_o, cB, 512, 0);
            ob.g[1] = ob.g[0];
            ob.g[2] = ob.g[0];
            sgemm_tpl<64, 64, 16, 4, 4><<<dim3(2, 16, 1), 256>>>(ob);
        }
    }

    k_gen_out<<<cT * 128, 256>>>(out, key0[cT - 1], key1[cT - 1]);
}

// round 6
// speedup vs baseline: 1.7160x; 1.7160x over previous
#include <cuda_runtime.h>
#include <cstdint>
#include <cmath>

// ---------------- problem constants ----------------
constexpr int cB = 128, cT = 128, cE = 1024, cH = 1024, cNH = 8, cA = 64;
constexpr int cKV = cNH * cA;          // 512
constexpr int BE  = cB * cE;           // 131072

// ---------------- persistent device scratch ----------------
__device__ float g_MUS [cT * BE];          // (T,B,E)
__device__ float g_SIGS[cT * BE];          // (T,B,E)
__device__ float g_S   [cT * BE];          // (T,B,E)
__device__ float g_X   [cB * 2048];        // [encs | context]
__device__ float g_H   [cB * cH];
__device__ float g_GIE [cB * 3072];        // encs @ W_ih[:, :E]^T (once)
__device__ float g_GI2 [2][cB * 3072];     // ctx-half gi, k-split partials
__device__ float g_GH2 [2][cB * 3072];     // gh k-split partials
__device__ float g_MSP [4][cB * cE];       // mu/sig k-split partials (0,1=mu; 2,3=sig)
__device__ float g_Q   [cB * cKV];
__device__ float g_U   [cB * cNH * cE];    // (b,h,e)

struct Ptrs { const float* w[17]; };
__device__ Ptrs g_ptr;

// ---------------- threefry2x32 (jax-exact) ----------------
__device__ __forceinline__ uint2 tf2x32(unsigned k0, unsigned k1, unsigned x0, unsigned x1) {
    unsigned k2 = k0 ^ k1 ^ 0x1BD11BDAu;
    x0 += k0; x1 += k1;
#define TFR(r) x0 += x1; x1 = __funnelshift_l(x1, x1, r); x1 ^= x0;
    TFR(13) TFR(15) TFR(26) TFR(6)   x0 += k1; x1 += k2 + 1u;
    TFR(17) TFR(29) TFR(16) TFR(24)  x0 += k2; x1 += k0 + 2u;
    TFR(13) TFR(15) TFR(26) TFR(6)   x0 += k0; x1 += k1 + 3u;
    TFR(17) TFR(29) TFR(16) TFR(24)  x0 += k1; x1 += k2 + 4u;
    TFR(13) TFR(15) TFR(26) TFR(6)   x0 += k2; x1 += k0 + 5u;
#undef TFR
    return make_uint2(x0, x1);
}
__device__ __forceinline__ uint2 step_key(int i) { return tf2x32(0u, 1234u, 0u, (unsigned)i); }

// uniform-bits -> N(0,1): jax _uniform + sqrt(2)*erf_inv (XLA Giles poly)
__device__ __forceinline__ float tf_normal(unsigned bits) {
    float f = __uint_as_float((bits >> 9) | 0x3f800000u) - 1.0f;
    float u = fmaf(f, 2.0f, -0.99999994f);
    u = fmaxf(u, -0.99999994f);
    float w = -log1pf(-u * u);
    float p;
    if (w < 5.0f) {
        w -= 2.5f;
        p = 2.81022636e-08f;
        p = fmaf(p, w, 3.43273939e-07f);
        p = fmaf(p, w, -3.5233877e-06f);
        p = fmaf(p, w, -4.39150654e-06f);
        p = fmaf(p, w, 0.00021858087f);
        p = fmaf(p, w, -0.00125372503f);
        p = fmaf(p, w, -0.00417768164f);
        p = fmaf(p, w, 0.246640727f);
        p = fmaf(p, w, 1.50140941f);
    } else {
        w = sqrtf(w) - 3.0f;
        p = -0.000200214257f;
        p = fmaf(p, w, 0.000100950558f);
        p = fmaf(p, w, 0.00134934322f);
        p = fmaf(p, w, -0.00367342844f);
        p = fmaf(p, w, 0.00573950773f);
        p = fmaf(p, w, -0.0076224613f);
        p = fmaf(p, w, 0.00943887047f);
        p = fmaf(p, w, 1.00167406f);
        p = fmaf(p, w, 2.83297682f);
    }
    return 1.4142135623730951f * (p * u);
}
__device__ __forceinline__ float eps_at(unsigned k0, unsigned k1, unsigned idx) {
    uint2 r = tf2x32(k0, k1, 0u, idx);
    return tf_normal(r.x ^ r.y);
}
__device__ __forceinline__ float softplusf(float x) {
    return fmaxf(x, 0.f) + log1pf(expf(-fabsf(x)));
}

// ---------------- setup + init ----------------
__global__ void k_setup(Ptrs p) { g_ptr = p; }
__global__ void k_init() {
    int idx = blockIdx.x * 256 + threadIdx.x;
    const float* encs = g_ptr.w[0];
    if (idx < cB * 2048) {
        int b = idx >> 11, c = idx & 2047;
        g_X[idx] = (c < cE) ? encs[b * cE + c] : 0.f;
    }
    if (idx < cB * cH) g_H[idx] = 0.f;
}

// ---------------- SGEMM 64x64x16, 256 threads, 4x4 microtile ----------------
enum { SEL_EB = 0, SEL_GB, SEL_MS, SEL_QB, SEL_UB };

struct GemmDesc {
    const float* A; const float* Bm; float* C; const float* bias;
    int lda, ldb, ldc, K, transB;
};

__device__ __forceinline__ GemmDesc get_desc(int sel, int z, int i) {
    GemmDesc d;
    d.bias = nullptr; d.transB = 0;
    switch (sel) {
    case SEL_EB:
        d.A = g_ptr.w[0]; d.lda = 1024;
        d.Bm = g_ptr.w[1]; d.ldb = 2048; d.transB = 1;
        d.C = g_GIE; d.ldc = 3072; d.K = 1024; break;
    case SEL_GB: {
        int kh = z & 1;
        if ((z >> 1) == 0) {
            d.A = g_X + 1024 + kh * 512; d.lda = 2048;
            d.Bm = g_ptr.w[1] + 1024 + kh * 512; d.ldb = 2048; d.transB = 1;
            d.C = g_GI2[kh]; d.ldc = 3072; d.K = 512;
        } else {
            d.A = g_H + kh * 512; d.lda = 1024;
            d.Bm = g_ptr.w[2] + kh * 512; d.ldb = 1024; d.transB = 1;
            d.C = g_GH2[kh]; d.ldc = 3072; d.K = 512;
        }
        break; }
    case SEL_MS: {
        int kh = z & 1, ms = z >> 1;  // 0=mu 1=sig
        d.A = g_H + kh * 512; d.lda = 1024; d.K = 512;
        d.Bm = (ms ? g_ptr.w[7] : g_ptr.w[5]) + (size_t)kh * 512 * 1024; d.ldb = 1024;
        d.C = g_MSP[z]; d.ldc = 1024; break; }
    case SEL_QB:
        d.A = g_S + (size_t)i * BE; d.lda = 1024;
        d.Bm = g_ptr.w[9]; d.ldb = 512;
        d.C = g_Q; d.ldc = 512; d.bias = g_ptr.w[10]; d.K = 1024; break;
    default: // SEL_UB, z = head
        d.A = g_Q + z * 64; d.lda = 512;
        d.Bm = g_ptr.w[11] + z * 64; d.ldb = 512; d.transB = 1;
        d.C = g_U + z * 1024; d.ldc = 8192; d.K = 64; break;
    }
    return d;
}

__global__ __launch_bounds__(256) void k_gemm(int sel, int i) {
    GemmDesc d = get_desc(sel, blockIdx.z, i);
    int m0 = blockIdx.x * 64, n0 = blockIdx.y * 64;

    __shared__ __align__(16) float As[16][64];
    __shared__ __align__(16) float Bs[16][64];

    int tid = threadIdx.x;
    int tx = tid & 15, ty = tid >> 4;

    float acc[4][4];
#pragma unroll
    for (int r = 0; r < 4; r++)
#pragma unroll
        for (int c = 0; c < 4; c++) acc[r][c] = 0.f;

    for (int k0 = 0; k0 < d.K; k0 += 16) {
        {   // A tile 64x16
            int row = tid >> 2, kc = (tid & 3) << 2;
            float4 v = *reinterpret_cast<const float4*>(d.A + (size_t)(m0 + row) * d.lda + k0 + kc);
            As[kc + 0][row] = v.x; As[kc + 1][row] = v.y;
            As[kc + 2][row] = v.z; As[kc + 3][row] = v.w;
        }
        if (!d.transB) {
            int kk = tid >> 4, nc = (tid & 15) << 2;
            *reinterpret_cast<float4*>(&Bs[kk][nc]) =
                *reinterpret_cast<const float4*>(d.Bm + (size_t)(k0 + kk) * d.ldb + n0 + nc);
        } else {
            int nn = tid >> 2, kc = (tid & 3) << 2;
            float4 v = *reinterpret_cast<const float4*>(d.Bm + (size_t)(n0 + nn) * d.ldb + k0 + kc);
            Bs[kc + 0][nn] = v.x; Bs[kc + 1][nn] = v.y;
            Bs[kc + 2][nn] = v.z; Bs[kc + 3][nn] = v.w;
        }
        __syncthreads();
#pragma unroll
        for (int kk = 0; kk < 16; kk++) {
            float4 a4 = *reinterpret_cast<const float4*>(&As[kk][ty * 4]);
            float4 b4 = *reinterpret_cast<const float4*>(&Bs[kk][tx * 4]);
            float af[4] = {a4.x, a4.y, a4.z, a4.w};
            float bf[4] = {b4.x, b4.y, b4.z, b4.w};
#pragma unroll
            for (int r = 0; r < 4; r++)
#pragma unroll
                for (int c = 0; c < 4; c++) acc[r][c] = fmaf(af[r], bf[c], acc[r][c]);
        }
        __syncthreads();
    }

    float4 bv = d.bias ? *reinterpret_cast<const float4*>(d.bias + n0 + tx * 4)
                       : make_float4(0.f, 0.f, 0.f, 0.f);
#pragma unroll
    for (int r = 0; r < 4; r++) {
        int m = m0 + ty * 4 + r;
        float4 v;
        v.x = acc[r][0] + bv.x; v.y = acc[r][1] + bv.y;
        v.z = acc[r][2] + bv.z; v.w = acc[r][3] + bv.w;
        *reinterpret_cast<float4*>(d.C + (size_t)m * d.ldc + n0 + tx * 4) = v;
    }
}

// ---------------- GRU gate combine (sums k-split partials) ----------------
__global__ void k_combine() {
    int idx = blockIdx.x * 256 + threadIdx.x;
    int b = idx >> 10, m = idx & 1023;
    const float* b_ih = g_ptr.w[3];
    const float* b_hh = g_ptr.w[4];
    int o = b * 3072;
    float ir = g_GIE[o + m]        + g_GI2[0][o + m]        + g_GI2[1][o + m]        + b_ih[m];
    float iz = g_GIE[o + m + 1024] + g_GI2[0][o + m + 1024] + g_GI2[1][o + m + 1024] + b_ih[m + 1024];
    float in = g_GIE[o + m + 2048] + g_GI2[0][o + m + 2048] + g_GI2[1][o + m + 2048] + b_ih[m + 2048];
    float hr = g_GH2[0][o + m]        + g_GH2[1][o + m]        + b_hh[m];
    float hz = g_GH2[0][o + m + 1024] + g_GH2[1][o + m + 1024] + b_hh[m + 1024];
    float hn = g_GH2[0][o + m + 2048] + g_GH2[1][o + m + 2048] + b_hh[m + 2048];
    float r = 1.f / (1.f + expf(-(ir + hr)));
    float z = 1.f / (1.f + expf(-(iz + hz)));
    float n = tanhf(fmaf(r, hn, in));
    float h = g_H[idx];
    g_H[idx] = fmaf(z, h - n, n);
}

// ---------------- gen_s: finalize row i from MS partials, sample all rows ---
__global__ __launch_bounds__(256) void k_gen_s(int i) {
    int b = blockIdx.x & 127;
    int j = blockIdx.x >> 7;
    int e = threadIdx.x << 2;
    uint2 kk = step_key(i);
    size_t off = (size_t)(j * cB + b) * cE + e;
    float4 mu, sg;
    if (j == i) {
        int q = b * 1024 + e;
        const float* bm = g_ptr.w[6];
        const float* bs = g_ptr.w[8];
        float4 m0 = *reinterpret_cast<const float4*>(&g_MSP[0][q]);
        float4 m1 = *reinterpret_cast<const float4*>(&g_MSP[1][q]);
        float4 s0 = *reinterpret_cast<const float4*>(&g_MSP[2][q]);
        float4 s1 = *reinterpret_cast<const float4*>(&g_MSP[3][q]);
        float4 bm4 = *reinterpret_cast<const float4*>(bm + e);
        float4 bs4 = *reinterpret_cast<const float4*>(bs + e);
        mu.x = m0.x + m1.x + bm4.x; mu.y = m0.y + m1.y + bm4.y;
        mu.z = m0.z + m1.z + bm4.z; mu.w = m0.w + m1.w + bm4.w;
        sg.x = softplusf(s0.x + s1.x + bs4.x); sg.y = softplusf(s0.y + s1.y + bs4.y);
        sg.z = softplusf(s0.z + s1.z + bs4.z); sg.w = softplusf(s0.w + s1.w + bs4.w);
        *reinterpret_cast<float4*>(g_MUS + off) = mu;
        *reinterpret_cast<float4*>(g_SIGS + off) = sg;
    } else {
        mu = *reinterpret_cast<const float4*>(g_MUS + off);
        sg = *reinterpret_cast<const float4*>(g_SIGS + off);
    }
    unsigned p = (unsigned)((b * cT + j) * cE + e);
    float4 s;
    s.x = fmaf(eps_at(kk.x, kk.y, p + 0), sg.x, mu.x);
    s.y = fmaf(eps_at(kk.x, kk.y, p + 1), sg.y, mu.y);
    s.z = fmaf(eps_at(kk.x, kk.y, p + 2), sg.z, mu.z);
    s.w = fmaf(eps_at(kk.x, kk.y, p + 3), sg.w, mu.w);
    *reinterpret_cast<float4*>(g_S + off) = s;
}

// finalize-only (step 127: no attention, but row must be finalized for output)
__global__ __launch_bounds__(256) void k_msfix(int i) {
    int b = blockIdx.x;
    int e = threadIdx.x << 2;
    int q = b * 1024 + e;
    size_t off = (size_t)(i * cB + b) * cE + e;
    const float* bm = g_ptr.w[6];
    const float* bs = g_ptr.w[8];
    float4 m0 = *reinterpret_cast<const float4*>(&g_MSP[0][q]);
    float4 m1 = *reinterpret_cast<const float4*>(&g_MSP[1][q]);
    float4 s0 = *reinterpret_cast<const float4*>(&g_MSP[2][q]);
    float4 s1 = *reinterpret_cast<const float4*>(&g_MSP[3][q]);
    float4 bm4 = *reinterpret_cast<const float4*>(bm + e);
    float4 bs4 = *reinterpret_cast<const float4*>(bs + e);
    float4 mu, sg;
    mu.x = m0.x + m1.x + bm4.x; mu.y = m0.y + m1.y + bm4.y;
    mu.z = m0.z + m1.z + bm4.z; mu.w = m0.w + m1.w + bm4.w;
    sg.x = softplusf(s0.x + s1.x + bs4.x); sg.y = softplusf(s0.y + s1.y + bs4.y);
    sg.z = softplusf(s0.z + s1.z + bs4.z); sg.w = softplusf(s0.w + s1.w + bs4.w);
    *reinterpret_cast<float4*>(g_MUS + off) = mu;
    *reinterpret_cast<float4*>(g_SIGS + off) = sg;
}

// ---------------- mega attention: scores+softmax+z+W_v+W_o, block per b -----
__global__ __launch_bounds__(512) void k_attn(int i) {
    int b = blockIdx.x;
    int nj = i + 1;
    int tid = threadIdx.x;

    __shared__ __align__(16) float zu_s[8192];  // u (pass1), then z (pass2+)
    __shared__ __align__(16) float w_s[1024];   // scores/weights, then ctx
    float* u_s = zu_s;

    // load u for this b (8 heads x 1024)
    {
        const float4* up = reinterpret_cast<const float4*>(g_U + (size_t)b * 8192);
        float4* us4 = reinterpret_cast<float4*>(u_s);
#pragma unroll
        for (int r = 0; r < 4; r++) us4[tid + r * 512] = up[tid + r * 512];
    }
    __syncthreads();

    int w = tid >> 5, l = tid & 31;
    int jr = w >> 3, h = w & 7;   // warp handles (row offset jr, head h)

    // ---- pass 1: raw scores, 2 j's per iteration ----
    for (int j0 = 0; j0 < nj; j0 += 2) {
        int j = j0 + jr;
        if (j < nj) {
            const float4* sp = reinterpret_cast<const float4*>(g_S + (size_t)(j * cB + b) * cE);
            const float4* uv4 = reinterpret_cast<const float4*>(u_s + h * 1024);
            float acc = 0.f;
#pragma unroll
            for (int k = 0; k < 8; k++) {
                float4 sv = sp[l + 32 * k];
                float4 uv = uv4[l + 32 * k];
                acc = fmaf(sv.x, uv.x, acc); acc = fmaf(sv.y, uv.y, acc);
                acc = fmaf(sv.z, uv.z, acc); acc = fmaf(sv.w, uv.w, acc);
            }
#pragma unroll
            for (int o = 16; o; o >>= 1) acc += __shfl_xor_sync(0xffffffffu, acc, o);
            if (l == 0) w_s[h * 128 + j] = acc * 0.125f;  // 1/sqrt(64)
        }
    }
    __syncthreads();

    // ---- softmax per head (warps 0..7) ----
    if (w < 8) {
        float v[4];
#pragma unroll
        for (int c = 0; c < 4; c++) {
            int j = l + 32 * c;
            v[c] = (j < nj) ? w_s[w * 128 + j] : -3.0e38f;
        }
        float m = fmaxf(fmaxf(v[0], v[1]), fmaxf(v[2], v[3]));
#pragma unroll
        for (int o = 16; o; o >>= 1) m = fmaxf(m, __shfl_xor_sync(0xffffffffu, m, o));
        float e[4], sum = 0.f;
#pragma unroll
        for (int c = 0; c < 4; c++) {
            int j = l + 32 * c;
            e[c] = (j < nj) ? expf(v[c] - m) : 0.f;
            sum += e[c];
        }
#pragma unroll
        for (int o = 16; o; o >>= 1) sum += __shfl_xor_sync(0xffffffffu, sum, o);
        float inv = 1.f / sum;
#pragma unroll
        for (int c = 0; c < 4; c++) {
            int j = l + 32 * c;
            if (j < nj) w_s[w * 128 + j] = e[c] * inv;
        }
    }
    __syncthreads();

    // ---- pass 2: z[h][e] = sum_j w[h][j] s[j][e]; each thread 2 e's --------
    int e0 = tid << 1;
    float za[8][2];
#pragma unroll
    for (int hh = 0; hh < 8; hh++) { za[hh][0] = 0.f; za[hh][1] = 0.f; }
    for (int j = 0; j < nj; j++) {
        float2 sv = *reinterpret_cast<const float2*>(g_S + (size_t)(j * cB + b) * cE + e0);
#pragma unroll
        for (int hh = 0; hh < 8; hh++) {
            float wj = w_s[hh * 128 + j];
            za[hh][0] = fmaf(wj, sv.x, za[hh][0]);
            za[hh][1] = fmaf(wj, sv.y, za[hh][1]);
        }
    }
    __syncthreads();   // u reads done; safe to overwrite zu_s with z
#pragma unroll
    for (int hh = 0; hh < 8; hh++) {
        zu_s[hh * 1024 + e0 + 0] = za[hh][0];
        zu_s[hh * 1024 + e0 + 1] = za[hh][1];
    }
    __syncthreads();

    // ---- pass 3: ctx[c] = sum_e z[h][e] W_v[e][c] + b_v[c], c = tid --------
    {
        const float* Wv = g_ptr.w[13];
        const float* bv = g_ptr.w[14];
        int hh = tid >> 6;
        const float* zrow = zu_s + hh * 1024;
        float acc = 0.f;
#pragma unroll 4
        for (int e = 0; e < 1024; e++)
            acc = fmaf(zrow[e], Wv[(size_t)e * 512 + tid], acc);
        float ctx = acc + bv[tid];
        __syncthreads();   // all w_s reads done (pass2 complete for all threads)
        w_s[tid] = ctx;    // reuse w_s[0..511] for ctx
    }
    __syncthreads();

    // ---- pass 4: X[b, E + e'] = sum_c ctx[c] W_o[c][e'] + b_o[e'] ----------
    {
        const float* Wo = g_ptr.w[15];
        const float* bo = g_ptr.w[16];
#pragma unroll
        for (int rep = 0; rep < 2; rep++) {
            int ep = tid + rep * 512;
            float acc = 0.f;
#pragma unroll 4
            for (int c = 0; c < 512; c++)
                acc = fmaf(w_s[c], Wo[(size_t)c * 1024 + ep], acc);
            g_X[b * 2048 + 1024 + ep] = acc + bo[ep];
        }
    }
}

// ---------------- final output (B,T,E): step-127 noise ----------------
__global__ __launch_bounds__(256) void k_genout(float* __restrict__ out) {
    int b = blockIdx.x & 127;
    int j = blockIdx.x >> 7;
    int e = threadIdx.x << 2;
    uint2 kk = step_key(cT - 1);
    size_t off = (size_t)(j * cB + b) * cE + e;
    float4 mu = *reinterpret_cast<const float4*>(g_MUS + off);
    float4 sg = *reinterpret_cast<const float4*>(g_SIGS + off);
    unsigned p = (unsigned)((b * cT + j) * cE + e);
    float4 s;
    s.x = fmaf(eps_at(kk.x, kk.y, p + 0), sg.x, mu.x);
    s.y = fmaf(eps_at(kk.x, kk.y, p + 1), sg.y, mu.y);
    s.z = fmaf(eps_at(kk.x, kk.y, p + 2), sg.z, mu.z);
    s.w = fmaf(eps_at(kk.x, kk.y, p + 3), sg.w, mu.w);
    *reinterpret_cast<float4*>(out + p) = s;
}

// ---------------- host side ----------------
extern "C" void kernel_launch(void* const* d_in, const int* in_sizes, int n_in,
                              void* d_out, int out_size) {
    Ptrs P;
    for (int k = 0; k < 17; k++) P.w[k] = (const float*)d_in[k];
    float* out = (float*)d_out;

    k_setup<<<1, 1>>>(P);
    k_init<<<1024, 256>>>();
    k_gemm<<<dim3(2, 48, 1), 256>>>(SEL_EB, 0);     // encs half of gi (once)

    for (int i = 0; i < cT; i++) {
        k_gemm<<<dim3(2, 48, 4), 256>>>(SEL_GB, i); // GIC/GH, k-split x2
        k_combine<<<512, 256>>>();
        k_gemm<<<dim3(2, 16, 4), 256>>>(SEL_MS, i); // mu/sig partials, k-split x2

        if (i < cT - 1) {
            k_gen_s<<<(i + 1) * cB, 256>>>(i);      // finalize row i + sample s
            k_gemm<<<dim3(2, 8, 1), 256>>>(SEL_QB, i);
            k_gemm<<<dim3(2, 16, 8), 256>>>(SEL_UB, i);
            k_attn<<<cB, 512>>>(i);                 // scores+softmax+z+Wv+Wo
        } else {
            k_msfix<<<cB, 256>>>(i);                // finalize last mu/sig row
        }
    }

    k_genout<<<cT * cB, 256>>>(out);
}

// round 7
// speedup vs baseline: 2.0356x; 1.1862x over previous
#include <cuda_runtime.h>
#include <cstdint>
#include <cmath>

// ---------------- problem constants ----------------
constexpr int cB = 128, cT = 128, cE = 1024, cH = 1024, cNH = 8, cA = 64;
constexpr int cKV = cNH * cA;          // 512
constexpr int BE  = cB * cE;           // 131072

// ---------------- persistent device scratch ----------------
__device__ float g_MUS [cT * BE];          // (T,B,E)
__device__ float g_SIGS[cT * BE];          // (T,B,E)
__device__ float g_S   [cT * BE];          // (T,B,E)
__device__ float g_X   [cB * 2048];        // [encs | context]
__device__ float g_H   [cB * cH];
__device__ float g_GIE [cB * 3072];        // encs @ W_ih[:, :E]^T (once)
__device__ float g_GI4 [4][cB * 3072];     // ctx-half gi partials (ksplit4)
__device__ float g_GH4 [4][cB * 3072];     // gh partials (ksplit4)
__device__ float g_MSP [8][cB * cE];       // mu partials [0..3], sig partials [4..7]
__device__ float g_QP  [4][cB * cKV];      // q partials (ksplit4)
__device__ float g_U   [cB * cNH * cE];    // (b,h,e)

struct Ptrs { const float* w[17]; };
__device__ Ptrs g_ptr;

// ---------------- threefry2x32 (jax-exact) ----------------
__device__ __forceinline__ uint2 tf2x32(unsigned k0, unsigned k1, unsigned x0, unsigned x1) {
    unsigned k2 = k0 ^ k1 ^ 0x1BD11BDAu;
    x0 += k0; x1 += k1;
#define TFR(r) x0 += x1; x1 = __funnelshift_l(x1, x1, r); x1 ^= x0;
    TFR(13) TFR(15) TFR(26) TFR(6)   x0 += k1; x1 += k2 + 1u;
    TFR(17) TFR(29) TFR(16) TFR(24)  x0 += k2; x1 += k0 + 2u;
    TFR(13) TFR(15) TFR(26) TFR(6)   x0 += k0; x1 += k1 + 3u;
    TFR(17) TFR(29) TFR(16) TFR(24)  x0 += k1; x1 += k2 + 4u;
    TFR(13) TFR(15) TFR(26) TFR(6)   x0 += k2; x1 += k0 + 5u;
#undef TFR
    return make_uint2(x0, x1);
}
__device__ __forceinline__ uint2 step_key(int i) { return tf2x32(0u, 1234u, 0u, (unsigned)i); }

// uniform-bits -> N(0,1): jax _uniform + sqrt(2)*erf_inv (XLA Giles poly)
__device__ __forceinline__ float tf_normal(unsigned bits) {
    float f = __uint_as_float((bits >> 9) | 0x3f800000u) - 1.0f;
    float u = fmaf(f, 2.0f, -0.99999994f);
    u = fmaxf(u, -0.99999994f);
    float w = -log1pf(-u * u);
    float p;
    if (w < 5.0f) {
        w -= 2.5f;
        p = 2.81022636e-08f;
        p = fmaf(p, w, 3.43273939e-07f);
        p = fmaf(p, w, -3.5233877e-06f);
        p = fmaf(p, w, -4.39150654e-06f);
        p = fmaf(p, w, 0.00021858087f);
        p = fmaf(p, w, -0.00125372503f);
        p = fmaf(p, w, -0.00417768164f);
        p = fmaf(p, w, 0.246640727f);
        p = fmaf(p, w, 1.50140941f);
    } else {
        w = sqrtf(w) - 3.0f;
        p = -0.000200214257f;
        p = fmaf(p, w, 0.000100950558f);
        p = fmaf(p, w, 0.00134934322f);
        p = fmaf(p, w, -0.00367342844f);
        p = fmaf(p, w, 0.00573950773f);
        p = fmaf(p, w, -0.0076224613f);
        p = fmaf(p, w, 0.00943887047f);
        p = fmaf(p, w, 1.00167406f);
        p = fmaf(p, w, 2.83297682f);
    }
    return 1.4142135623730951f * (p * u);
}
__device__ __forceinline__ float eps_at(unsigned k0, unsigned k1, unsigned idx) {
    uint2 r = tf2x32(k0, k1, 0u, idx);
    return tf_normal(r.x ^ r.y);
}
__device__ __forceinline__ float softplusf(float x) {
    return fmaxf(x, 0.f) + log1pf(expf(-fabsf(x)));
}

// ---------------- setup + init ----------------
__global__ void k_setup(Ptrs p) { g_ptr = p; }
__global__ void k_init() {
    int idx = blockIdx.x * 256 + threadIdx.x;
    const float* encs = g_ptr.w[0];
    if (idx < cB * 2048) {
        int b = idx >> 11, c = idx & 2047;
        g_X[idx] = (c < cE) ? encs[b * cE + c] : 0.f;
    }
    if (idx < cB * cH) g_H[idx] = 0.f;
}

// ---------------- SGEMM: BM=128(all M), BN=64, BK=16, 128 thr, 8x8 microtile
enum { SEL_EB = 0, SEL_GB, SEL_MS, SEL_QB, SEL_UB };

struct GemmDesc {
    const float* A; const float* Bm; float* C; const float* qbias;
    int lda, ldb, ldc, K, transB, qsum;
};

__device__ __forceinline__ GemmDesc get_desc(int sel, int z, int i) {
    GemmDesc d; d.qbias = nullptr; d.transB = 0; d.qsum = 0;
    switch (sel) {
    case SEL_EB:
        d.A = g_ptr.w[0]; d.lda = 1024;
        d.Bm = g_ptr.w[1]; d.ldb = 2048; d.transB = 1;
        d.C = g_GIE; d.ldc = 3072; d.K = 1024; break;
    case SEL_GB: {
        int kh = z & 3;
        if ((z >> 2) == 0) {
            d.A = g_X + 1024 + kh * 256; d.lda = 2048;
            d.Bm = g_ptr.w[1] + 1024 + kh * 256; d.ldb = 2048; d.transB = 1;
            d.C = g_GI4[kh]; d.ldc = 3072; d.K = 256;
        } else {
            d.A = g_H + kh * 256; d.lda = 1024;
            d.Bm = g_ptr.w[2] + kh * 256; d.ldb = 1024; d.transB = 1;
            d.C = g_GH4[kh]; d.ldc = 3072; d.K = 256;
        }
        break; }
    case SEL_MS: {
        int kh = z & 3, ms = z >> 2;
        d.A = g_H + kh * 256; d.lda = 1024; d.K = 256;
        d.Bm = (ms ? g_ptr.w[7] : g_ptr.w[5]) + (size_t)kh * 256 * 1024; d.ldb = 1024;
        d.C = g_MSP[z]; d.ldc = 1024; break; }
    case SEL_QB:
        d.A = g_S + (size_t)i * BE + z * 256; d.lda = 1024; d.K = 256;
        d.Bm = g_ptr.w[9] + (size_t)z * 256 * 512; d.ldb = 512;
        d.C = g_QP[z]; d.ldc = 512; break;
    default: // SEL_UB, z = head
        d.qsum = 1;
        d.A = g_QP[0] + z * 64; d.lda = 512;
        d.qbias = g_ptr.w[10] + z * 64;
        d.Bm = g_ptr.w[11] + z * 64; d.ldb = 512; d.transB = 1;
        d.C = g_U + z * 1024; d.ldc = 8192; d.K = 64; break;
    }
    return d;
}

__global__ __launch_bounds__(128) void k_gemm(int sel, int i) {
    GemmDesc d = get_desc(sel, blockIdx.z, i);
    int n0 = blockIdx.y * 64;

    __shared__ __align__(16) float As[16][132];
    __shared__ __align__(16) float Bs[16][68];

    int tid = threadIdx.x;
    int tx = tid & 7, ty = tid >> 3;

    float acc[8][8];
#pragma unroll
    for (int r = 0; r < 8; r++)
#pragma unroll
        for (int c = 0; c < 8; c++) acc[r][c] = 0.f;

    for (int k0 = 0; k0 < d.K; k0 += 16) {
        // A tile 128x16 (4 float4 per thread)
#pragma unroll
        for (int r = 0; r < 4; r++) {
            int q = tid + r * 128;
            int row = q >> 2, kc = (q & 3) << 2;
            const float* ap = d.A + (size_t)row * d.lda + k0 + kc;
            float4 v;
            if (!d.qsum) {
                v = *reinterpret_cast<const float4*>(ap);
            } else {
                float4 v0 = *reinterpret_cast<const float4*>(ap);
                float4 v1 = *reinterpret_cast<const float4*>(ap + 65536);
                float4 v2 = *reinterpret_cast<const float4*>(ap + 131072);
                float4 v3 = *reinterpret_cast<const float4*>(ap + 196608);
                float4 bb = *reinterpret_cast<const float4*>(d.qbias + k0 + kc);
                v.x = v0.x + v1.x + v2.x + v3.x + bb.x;
                v.y = v0.y + v1.y + v2.y + v3.y + bb.y;
                v.z = v0.z + v1.z + v2.z + v3.z + bb.z;
                v.w = v0.w + v1.w + v2.w + v3.w + bb.w;
            }
            As[kc + 0][row] = v.x; As[kc + 1][row] = v.y;
            As[kc + 2][row] = v.z; As[kc + 3][row] = v.w;
        }
        // B tile 16x64 (2 float4 per thread)
        if (!d.transB) {
#pragma unroll
            for (int r = 0; r < 2; r++) {
                int q = tid + r * 128;
                int kk = q >> 4, nc = (q & 15) << 2;
                *reinterpret_cast<float4*>(&Bs[kk][nc]) =
                    *reinterpret_cast<const float4*>(d.Bm + (size_t)(k0 + kk) * d.ldb + n0 + nc);
            }
        } else {
#pragma unroll
            for (int r = 0; r < 2; r++) {
                int q = tid + r * 128;
                int nn = q >> 2, kc = (q & 3) << 2;
                float4 v = *reinterpret_cast<const float4*>(
                    d.Bm + (size_t)(n0 + nn) * d.ldb + k0 + kc);
                Bs[kc + 0][nn] = v.x; Bs[kc + 1][nn] = v.y;
                Bs[kc + 2][nn] = v.z; Bs[kc + 3][nn] = v.w;
            }
        }
        __syncthreads();
#pragma unroll
        for (int kk = 0; kk < 16; kk++) {
            float4 a0 = *reinterpret_cast<const float4*>(&As[kk][ty * 8]);
            float4 a1 = *reinterpret_cast<const float4*>(&As[kk][ty * 8 + 4]);
            float4 b0 = *reinterpret_cast<const float4*>(&Bs[kk][tx * 8]);
            float4 b1 = *reinterpret_cast<const float4*>(&Bs[kk][tx * 8 + 4]);
            float af[8] = {a0.x, a0.y, a0.z, a0.w, a1.x, a1.y, a1.z, a1.w};
            float bf[8] = {b0.x, b0.y, b0.z, b0.w, b1.x, b1.y, b1.z, b1.w};
#pragma unroll
            for (int r = 0; r < 8; r++)
#pragma unroll
                for (int c = 0; c < 8; c++) acc[r][c] = fmaf(af[r], bf[c], acc[r][c]);
        }
        __syncthreads();
    }
#pragma unroll
    for (int r = 0; r < 8; r++) {
        int m = ty * 8 + r;
        float4 v0 = make_float4(acc[r][0], acc[r][1], acc[r][2], acc[r][3]);
        float4 v1 = make_float4(acc[r][4], acc[r][5], acc[r][6], acc[r][7]);
        float* cp = d.C + (size_t)m * d.ldc + n0 + tx * 8;
        *reinterpret_cast<float4*>(cp) = v0;
        *reinterpret_cast<float4*>(cp + 4) = v1;
    }
}

// ---------------- GRU gate combine (sums ksplit4 partials) ----------------
__global__ void k_combine() {
    int idx = blockIdx.x * 256 + threadIdx.x;
    int b = idx >> 10, m = idx & 1023;
    const float* b_ih = g_ptr.w[3];
    const float* b_hh = g_ptr.w[4];
    int o = b * 3072;
    float ir = g_GIE[o + m] + b_ih[m];
    float iz = g_GIE[o + m + 1024] + b_ih[m + 1024];
    float in = g_GIE[o + m + 2048] + b_ih[m + 2048];
    float hr = b_hh[m], hz = b_hh[m + 1024], hn = b_hh[m + 2048];
#pragma unroll
    for (int p = 0; p < 4; p++) {
        ir += g_GI4[p][o + m];        iz += g_GI4[p][o + m + 1024];  in += g_GI4[p][o + m + 2048];
        hr += g_GH4[p][o + m];        hz += g_GH4[p][o + m + 1024];  hn += g_GH4[p][o + m + 2048];
    }
    float r = 1.f / (1.f + expf(-(ir + hr)));
    float z = 1.f / (1.f + expf(-(iz + hz)));
    float n = tanhf(fmaf(r, hn, in));
    float h = g_H[idx];
    g_H[idx] = fmaf(z, h - n, n);
}

// ---------------- gen_s: finalize row i from MS partials, sample all rows ---
__global__ __launch_bounds__(256) void k_gen_s(int i) {
    int b = blockIdx.x & 127;
    int j = blockIdx.x >> 7;
    int e = threadIdx.x << 2;
    uint2 kk = step_key(i);
    size_t off = (size_t)(j * cB + b) * cE + e;
    float4 mu, sg;
    if (j == i) {
        int q = b * 1024 + e;
        float4 bm4 = *reinterpret_cast<const float4*>(g_ptr.w[6] + e);
        float4 bs4 = *reinterpret_cast<const float4*>(g_ptr.w[8] + e);
        mu = bm4; sg = bs4;
#pragma unroll
        for (int p = 0; p < 4; p++) {
            float4 mp = *reinterpret_cast<const float4*>(&g_MSP[p][q]);
            float4 sp = *reinterpret_cast<const float4*>(&g_MSP[p + 4][q]);
            mu.x += mp.x; mu.y += mp.y; mu.z += mp.z; mu.w += mp.w;
            sg.x += sp.x; sg.y += sp.y; sg.z += sp.z; sg.w += sp.w;
        }
        sg.x = softplusf(sg.x); sg.y = softplusf(sg.y);
        sg.z = softplusf(sg.z); sg.w = softplusf(sg.w);
        *reinterpret_cast<float4*>(g_MUS + off) = mu;
        *reinterpret_cast<float4*>(g_SIGS + off) = sg;
    } else {
        mu = *reinterpret_cast<const float4*>(g_MUS + off);
        sg = *reinterpret_cast<const float4*>(g_SIGS + off);
    }
    unsigned p = (unsigned)((b * cT + j) * cE + e);
    float4 s;
    s.x = fmaf(eps_at(kk.x, kk.y, p + 0), sg.x, mu.x);
    s.y = fmaf(eps_at(kk.x, kk.y, p + 1), sg.y, mu.y);
    s.z = fmaf(eps_at(kk.x, kk.y, p + 2), sg.z, mu.z);
    s.w = fmaf(eps_at(kk.x, kk.y, p + 3), sg.w, mu.w);
    *reinterpret_cast<float4*>(g_S + off) = s;
}

// finalize-only (step 127: no attention, but row must be finalized for output)
__global__ __launch_bounds__(256) void k_msfix(int i) {
    int b = blockIdx.x;
    int e = threadIdx.x << 2;
    int q = b * 1024 + e;
    size_t off = (size_t)(i * cB + b) * cE + e;
    float4 mu = *reinterpret_cast<const float4*>(g_ptr.w[6] + e);
    float4 sg = *reinterpret_cast<const float4*>(g_ptr.w[8] + e);
#pragma unroll
    for (int p = 0; p < 4; p++) {
        float4 mp = *reinterpret_cast<const float4*>(&g_MSP[p][q]);
        float4 sp = *reinterpret_cast<const float4*>(&g_MSP[p + 4][q]);
        mu.x += mp.x; mu.y += mp.y; mu.z += mp.z; mu.w += mp.w;
        sg.x += sp.x; sg.y += sp.y; sg.z += sp.z; sg.w += sp.w;
    }
    sg.x = softplusf(sg.x); sg.y = softplusf(sg.y);
    sg.z = softplusf(sg.z); sg.w = softplusf(sg.w);
    *reinterpret_cast<float4*>(g_MUS + off) = mu;
    *reinterpret_cast<float4*>(g_SIGS + off) = sg;
}

// ---------------- mega attention: 4 b's per block, 32 blocks, 512 threads ---
// dyn smem: zu[4*8192] (u then z) + w_s[4096] (scores/weights then ctx)
__global__ __launch_bounds__(512) void k_attn(int i) {
    extern __shared__ float sm[];
    float* zu = sm;            // 32768 floats
    float* w_s = sm + 32768;   // 4096 floats
    int bb = blockIdx.x;       // 0..31
    int nj = i + 1;
    int tid = threadIdx.x;
    int w = tid >> 5, l = tid & 31;

    // load u for 4 b's
    {
        const float4* src = reinterpret_cast<const float4*>(g_U + (size_t)bb * 32768);
        float4* dst = reinterpret_cast<float4*>(zu);
#pragma unroll
        for (int r = 0; r < 16; r++) dst[tid + r * 512] = src[tid + r * 512];
    }
    __syncthreads();

    // ---- pass 1: scores for 32 (bl,h) combos; each warp 2 combos ----
#pragma unroll
    for (int rep = 0; rep < 2; rep++) {
        int c = w + rep * 16;
        int bl = c >> 3, h = c & 7;
        int b = bb * 4 + bl;
        const float4* uv4 = reinterpret_cast<const float4*>(zu + bl * 8192 + h * 1024);
        for (int j = 0; j < nj; j++) {
            const float4* sp = reinterpret_cast<const float4*>(g_S + (size_t)(j * cB + b) * cE);
            float acc = 0.f;
#pragma unroll
            for (int k = 0; k < 8; k++) {
                float4 sv = sp[l + 32 * k];
                float4 uv = uv4[l + 32 * k];
                acc = fmaf(sv.x, uv.x, acc); acc = fmaf(sv.y, uv.y, acc);
                acc = fmaf(sv.z, uv.z, acc); acc = fmaf(sv.w, uv.w, acc);
            }
#pragma unroll
            for (int o = 16; o; o >>= 1) acc += __shfl_xor_sync(0xffffffffu, acc, o);
            if (l == 0) w_s[c * 128 + j] = acc * 0.125f;   // 1/sqrt(64)
        }
    }
    __syncthreads();

    // ---- softmax per combo ----
#pragma unroll
    for (int rep = 0; rep < 2; rep++) {
        int c = w + rep * 16;
        float v[4];
#pragma unroll
        for (int cc = 0; cc < 4; cc++) {
            int j = l + 32 * cc;
            v[cc] = (j < nj) ? w_s[c * 128 + j] : -3.0e38f;
        }
        float m = fmaxf(fmaxf(v[0], v[1]), fmaxf(v[2], v[3]));
#pragma unroll
        for (int o = 16; o; o >>= 1) m = fmaxf(m, __shfl_xor_sync(0xffffffffu, m, o));
        float e[4], sum = 0.f;
#pragma unroll
        for (int cc = 0; cc < 4; cc++) {
            int j = l + 32 * cc;
            e[cc] = (j < nj) ? expf(v[cc] - m) : 0.f;
            sum += e[cc];
        }
#pragma unroll
        for (int o = 16; o; o >>= 1) sum += __shfl_xor_sync(0xffffffffu, sum, o);
        float inv = 1.f / sum;
#pragma unroll
        for (int cc = 0; cc < 4; cc++) {
            int j = l + 32 * cc;
            if (j < nj) w_s[c * 128 + j] = e[cc] * inv;
        }
    }
    __syncthreads();

    // ---- pass 2: z[bl][h][e] = sum_j w * s ; thread = (bl, 8 e's) ----
    {
        int bl = tid >> 7;
        int e0 = (tid & 127) << 3;
        int b = bb * 4 + bl;
        float za[8][8];
#pragma unroll
        for (int h = 0; h < 8; h++)
#pragma unroll
            for (int u = 0; u < 8; u++) za[h][u] = 0.f;
        for (int j = 0; j < nj; j++) {
            const float4* sp = reinterpret_cast<const float4*>(g_S + (size_t)(j * cB + b) * cE + e0);
            float4 s0 = sp[0], s1 = sp[1];
            float sv[8] = {s0.x, s0.y, s0.z, s0.w, s1.x, s1.y, s1.z, s1.w};
#pragma unroll
            for (int h = 0; h < 8; h++) {
                float wj = w_s[(bl * 8 + h) * 128 + j];
#pragma unroll
                for (int u = 0; u < 8; u++) za[h][u] = fmaf(wj, sv[u], za[h][u]);
            }
        }
        __syncthreads();   // all pass-1 u reads & pass-2 w reads complete
#pragma unroll
        for (int h = 0; h < 8; h++) {
            float4* zp = reinterpret_cast<float4*>(zu + bl * 8192 + h * 1024 + e0);
            zp[0] = make_float4(za[h][0], za[h][1], za[h][2], za[h][3]);
            zp[1] = make_float4(za[h][4], za[h][5], za[h][6], za[h][7]);
        }
    }
    __syncthreads();

    // ---- pass 3: ctx[bl][c] = sum_e z[bl][h(c)][e] Wv[e][c] + bv[c] ----
    {
        int bl = tid >> 7;
        int c4 = (tid & 127) << 2;
        int h = c4 >> 6;
        const float* zrow = zu + bl * 8192 + h * 1024;
        const float* Wv = g_ptr.w[13];
        float a0 = 0.f, a1 = 0.f, a2 = 0.f, a3 = 0.f;
        for (int e = 0; e < 1024; e++) {
            float zv = zrow[e];
            float4 wv = *reinterpret_cast<const float4*>(Wv + (size_t)e * 512 + c4);
            a0 = fmaf(zv, wv.x, a0); a1 = fmaf(zv, wv.y, a1);
            a2 = fmaf(zv, wv.z, a2); a3 = fmaf(zv, wv.w, a3);
        }
        float4 bv4 = *reinterpret_cast<const float4*>(g_ptr.w[14] + c4);
        *reinterpret_cast<float4*>(w_s + bl * 512 + c4) =
            make_float4(a0 + bv4.x, a1 + bv4.y, a2 + bv4.z, a3 + bv4.w);
    }
    __syncthreads();

    // ---- pass 4: X[b, E+e'] = sum_c ctx[bl][c] Wo[c][e'] + bo[e'] ----
    {
        int bl = tid >> 7;
        int e0 = (tid & 127) << 3;
        const float* Wo = g_ptr.w[15];
        float a[8];
#pragma unroll
        for (int u = 0; u < 8; u++) a[u] = 0.f;
        for (int c = 0; c < 512; c++) {
            float cv = w_s[bl * 512 + c];
            const float4* wo = reinterpret_cast<const float4*>(Wo + (size_t)c * 1024 + e0);
            float4 w0 = wo[0], w1 = wo[1];
            a[0] = fmaf(cv, w0.x, a[0]); a[1] = fmaf(cv, w0.y, a[1]);
            a[2] = fmaf(cv, w0.z, a[2]); a[3] = fmaf(cv, w0.w, a[3]);
            a[4] = fmaf(cv, w1.x, a[4]); a[5] = fmaf(cv, w1.y, a[5]);
            a[6] = fmaf(cv, w1.z, a[6]); a[7] = fmaf(cv, w1.w, a[7]);
        }
        const float* bo = g_ptr.w[16];
        float* xp = g_X + (bb * 4 + bl) * 2048 + 1024 + e0;
#pragma unroll
        for (int u = 0; u < 8; u++) xp[u] = a[u] + bo[e0 + u];
    }
}

// ---------------- final output (B,T,E): step-127 noise ----------------
__global__ __launch_bounds__(256) void k_genout(float* __restrict__ out) {
    int b = blockIdx.x & 127;
    int j = blockIdx.x >> 7;
    int e = threadIdx.x << 2;
    uint2 kk = step_key(cT - 1);
    size_t off = (size_t)(j * cB + b) * cE + e;
    float4 mu = *reinterpret_cast<const float4*>(g_MUS + off);
    float4 sg = *reinterpret_cast<const float4*>(g_SIGS + off);
    unsigned p = (unsigned)((b * cT + j) * cE + e);
    float4 s;
    s.x = fmaf(eps_at(kk.x, kk.y, p + 0), sg.x, mu.x);
    s.y = fmaf(eps_at(kk.x, kk.y, p + 1), sg.y, mu.y);
    s.z = fmaf(eps_at(kk.x, kk.y, p + 2), sg.z, mu.z);
    s.w = fmaf(eps_at(kk.x, kk.y, p + 3), sg.w, mu.w);
    *reinterpret_cast<float4*>(out + p) = s;
}

// ---------------- host side ----------------
extern "C" void kernel_launch(void* const* d_in, const int* in_sizes, int n_in,
                              void* d_out, int out_size) {
    Ptrs P;
    for (int k = 0; k < 17; k++) P.w[k] = (const float*)d_in[k];
    float* out = (float*)d_out;

    constexpr int ATTN_SMEM = (32768 + 4096) * 4;   // 147456 B
    cudaFuncSetAttribute(k_attn, cudaFuncAttributeMaxDynamicSharedMemorySize, ATTN_SMEM);

    k_setup<<<1, 1>>>(P);
    k_init<<<1024, 256>>>();
    k_gemm<<<dim3(1, 48, 1), 128>>>(SEL_EB, 0);     // encs half of gi (once)

    for (int i = 0; i < cT; i++) {
        k_gemm<<<dim3(1, 48, 8), 128>>>(SEL_GB, i); // GIC/GH, ksplit4
        k_combine<<<512, 256>>>();
        k_gemm<<<dim3(1, 16, 8), 128>>>(SEL_MS, i); // mu/sig partials, ksplit4

        if (i < cT - 1) {
            k_gen_s<<<(i + 1) * cB, 256>>>(i);      // finalize row i + sample s
            k_gemm<<<dim3(1, 8, 4), 128>>>(SEL_QB, i);   // q partials, ksplit4
            k_gemm<<<dim3(1, 16, 8), 128>>>(SEL_UB, i);  // u per head (sums q)
            k_attn<<<32, 512, ATTN_SMEM>>>(i);      // scores+softmax+z+Wv+Wo
        } else {
            k_msfix<<<cB, 256>>>(i);
        }
    }

    k_genout<<<cT * cB, 256>>>(out);
}

// round 8
// speedup vs baseline: 2.3186x; 1.1390x over previous
#include <cuda_runtime.h>
#include <cstdint>
#include <cmath>

// ---------------- problem constants ----------------
constexpr int cB = 128, cT = 128, cE = 1024, cH = 1024, cNH = 8, cA = 64;
constexpr int cKV = cNH * cA;          // 512
constexpr int BE  = cB * cE;           // 131072

// ---------------- persistent device scratch ----------------
__device__ float g_MUS [cT * BE];          // (T,B,E)
__device__ float g_SIGS[cT * BE];          // (T,B,E)
__device__ float g_S   [cT * BE];          // (T,B,E)
__device__ float g_X   [cB * 2048];        // [encs | context]
__device__ float g_H   [cB * cH];
__device__ float g_GIE [cB * 3072];        // encs @ W_ih[:, :E]^T (once)
__device__ float g_GI4 [4][cB * 3072];     // ctx-half gi partials (ksplit4)
__device__ float g_GH4 [4][cB * 3072];     // gh partials (ksplit4)
__device__ float g_MSP [8][cB * cE];       // mu partials [0..3], sig partials [4..7]
__device__ float g_QP  [4][cB * cKV];      // q partials (ksplit4)
__device__ float g_U   [cB * cNH * cE];    // (b,h,e)

struct Ptrs { const float* w[17]; };
__device__ Ptrs g_ptr;

// ---------------- threefry2x32 (jax-exact) ----------------
__device__ __forceinline__ uint2 tf2x32(unsigned k0, unsigned k1, unsigned x0, unsigned x1) {
    unsigned k2 = k0 ^ k1 ^ 0x1BD11BDAu;
    x0 += k0; x1 += k1;
#define TFR(r) x0 += x1; x1 = __funnelshift_l(x1, x1, r); x1 ^= x0;
    TFR(13) TFR(15) TFR(26) TFR(6)   x0 += k1; x1 += k2 + 1u;
    TFR(17) TFR(29) TFR(16) TFR(24)  x0 += k2; x1 += k0 + 2u;
    TFR(13) TFR(15) TFR(26) TFR(6)   x0 += k0; x1 += k1 + 3u;
    TFR(17) TFR(29) TFR(16) TFR(24)  x0 += k1; x1 += k2 + 4u;
    TFR(13) TFR(15) TFR(26) TFR(6)   x0 += k2; x1 += k0 + 5u;
#undef TFR
    return make_uint2(x0, x1);
}
__device__ __forceinline__ uint2 step_key(int i) { return tf2x32(0u, 1234u, 0u, (unsigned)i); }

// uniform-bits -> N(0,1): jax _uniform + sqrt(2)*erf_inv (XLA Giles poly)
__device__ __forceinline__ float tf_normal(unsigned bits) {
    float f = __uint_as_float((bits >> 9) | 0x3f800000u) - 1.0f;
    float u = fmaf(f, 2.0f, -0.99999994f);
    u = fmaxf(u, -0.99999994f);
    float w = -log1pf(-u * u);
    float p;
    if (w < 5.0f) {
        w -= 2.5f;
        p = 2.81022636e-08f;
        p = fmaf(p, w, 3.43273939e-07f);
        p = fmaf(p, w, -3.5233877e-06f);
        p = fmaf(p, w, -4.39150654e-06f);
        p = fmaf(p, w, 0.00021858087f);
        p = fmaf(p, w, -0.00125372503f);
        p = fmaf(p, w, -0.00417768164f);
        p = fmaf(p, w, 0.246640727f);
        p = fmaf(p, w, 1.50140941f);
    } else {
        w = sqrtf(w) - 3.0f;
        p = -0.000200214257f;
        p = fmaf(p, w, 0.000100950558f);
        p = fmaf(p, w, 0.00134934322f);
        p = fmaf(p, w, -0.00367342844f);
        p = fmaf(p, w, 0.00573950773f);
        p = fmaf(p, w, -0.0076224613f);
        p = fmaf(p, w, 0.00943887047f);
        p = fmaf(p, w, 1.00167406f);
        p = fmaf(p, w, 2.83297682f);
    }
    return 1.4142135623730951f * (p * u);
}
__device__ __forceinline__ float eps_at(unsigned k0, unsigned k1, unsigned idx) {
    uint2 r = tf2x32(k0, k1, 0u, idx);
    return tf_normal(r.x ^ r.y);
}
__device__ __forceinline__ float softplusf(float x) {
    return fmaxf(x, 0.f) + log1pf(expf(-fabsf(x)));
}

// ---------------- setup + init ----------------
__global__ void k_setup(Ptrs p) { g_ptr = p; }
__global__ void k_init() {
    int idx = blockIdx.x * 256 + threadIdx.x;
    const float* encs = g_ptr.w[0];
    if (idx < cB * 2048) {
        int b = idx >> 11, c = idx & 2047;
        g_X[idx] = (c < cE) ? encs[b * cE + c] : 0.f;
    }
    if (idx < cB * cH) g_H[idx] = 0.f;
}

// ---------------- SGEMM: BM=128(all M), BN=64, BK=16, 256 thr, 4x8 microtile
enum { SEL_EB = 0, SEL_GB, SEL_MS, SEL_QB, SEL_UB };

struct GemmDesc {
    const float* A; const float* Bm; float* C; const float* qbias;
    int lda, ldb, ldc, K, transB, qsum;
};

__device__ __forceinline__ GemmDesc get_desc(int sel, int z, int i) {
    GemmDesc d; d.qbias = nullptr; d.transB = 0; d.qsum = 0;
    switch (sel) {
    case SEL_EB:
        d.A = g_ptr.w[0]; d.lda = 1024;
        d.Bm = g_ptr.w[1]; d.ldb = 2048; d.transB = 1;
        d.C = g_GIE; d.ldc = 3072; d.K = 1024; break;
    case SEL_GB: {
        int kh = z & 3;
        if ((z >> 2) == 0) {
            d.A = g_X + 1024 + kh * 256; d.lda = 2048;
            d.Bm = g_ptr.w[1] + 1024 + kh * 256; d.ldb = 2048; d.transB = 1;
            d.C = g_GI4[kh]; d.ldc = 3072; d.K = 256;
        } else {
            d.A = g_H + kh * 256; d.lda = 1024;
            d.Bm = g_ptr.w[2] + kh * 256; d.ldb = 1024; d.transB = 1;
            d.C = g_GH4[kh]; d.ldc = 3072; d.K = 256;
        }
        break; }
    case SEL_MS: {
        int kh = z & 3, ms = z >> 2;
        d.A = g_H + kh * 256; d.lda = 1024; d.K = 256;
        d.Bm = (ms ? g_ptr.w[7] : g_ptr.w[5]) + (size_t)kh * 256 * 1024; d.ldb = 1024;
        d.C = g_MSP[z]; d.ldc = 1024; break; }
    case SEL_QB:
        d.A = g_S + (size_t)i * BE + z * 256; d.lda = 1024; d.K = 256;
        d.Bm = g_ptr.w[9] + (size_t)z * 256 * 512; d.ldb = 512;
        d.C = g_QP[z]; d.ldc = 512; break;
    default: // SEL_UB, z = head
        d.qsum = 1;
        d.A = g_QP[0] + z * 64; d.lda = 512;
        d.qbias = g_ptr.w[10] + z * 64;
        d.Bm = g_ptr.w[11] + z * 64; d.ldb = 512; d.transB = 1;
        d.C = g_U + z * 1024; d.ldc = 8192; d.K = 64; break;
    }
    return d;
}

__global__ __launch_bounds__(256) void k_gemm(int sel, int i) {
    GemmDesc d = get_desc(sel, blockIdx.z, i);
    int n0 = blockIdx.y * 64;

    __shared__ __align__(16) float As[16][132];
    __shared__ __align__(16) float Bs[16][68];

    int tid = threadIdx.x;
    int tx = tid & 7;    // n: 8 cols of 8
    int ty = tid >> 3;   // m: 32 rows of 4

    float acc[4][8];
#pragma unroll
    for (int r = 0; r < 4; r++)
#pragma unroll
        for (int c = 0; c < 8; c++) acc[r][c] = 0.f;

    for (int k0 = 0; k0 < d.K; k0 += 16) {
        // A tile 128x16: 2 float4 per thread
#pragma unroll
        for (int r = 0; r < 2; r++) {
            int q = tid + r * 256;
            int row = q >> 2, kc = (q & 3) << 2;
            const float* ap = d.A + (size_t)row * d.lda + k0 + kc;
            float4 v;
            if (!d.qsum) {
                v = *reinterpret_cast<const float4*>(ap);
            } else {
                float4 v0 = *reinterpret_cast<const float4*>(ap);
                float4 v1 = *reinterpret_cast<const float4*>(ap + 65536);
                float4 v2 = *reinterpret_cast<const float4*>(ap + 131072);
                float4 v3 = *reinterpret_cast<const float4*>(ap + 196608);
                float4 bb = *reinterpret_cast<const float4*>(d.qbias + k0 + kc);
                v.x = v0.x + v1.x + v2.x + v3.x + bb.x;
                v.y = v0.y + v1.y + v2.y + v3.y + bb.y;
                v.z = v0.z + v1.z + v2.z + v3.z + bb.z;
                v.w = v0.w + v1.w + v2.w + v3.w + bb.w;
            }
            As[kc + 0][row] = v.x; As[kc + 1][row] = v.y;
            As[kc + 2][row] = v.z; As[kc + 3][row] = v.w;
        }
        // B tile 16x64: 1 float4 per thread
        if (!d.transB) {
            int kk = tid >> 4, nc = (tid & 15) << 2;
            *reinterpret_cast<float4*>(&Bs[kk][nc]) =
                *reinterpret_cast<const float4*>(d.Bm + (size_t)(k0 + kk) * d.ldb + n0 + nc);
        } else {
            int nn = tid >> 2, kc = (tid & 3) << 2;
            float4 v = *reinterpret_cast<const float4*>(
                d.Bm + (size_t)(n0 + nn) * d.ldb + k0 + kc);
            Bs[kc + 0][nn] = v.x; Bs[kc + 1][nn] = v.y;
            Bs[kc + 2][nn] = v.z; Bs[kc + 3][nn] = v.w;
        }
        __syncthreads();
#pragma unroll
        for (int kk = 0; kk < 16; kk++) {
            float4 a4 = *reinterpret_cast<const float4*>(&As[kk][ty * 4]);
            float4 b0 = *reinterpret_cast<const float4*>(&Bs[kk][tx * 8]);
            float4 b1 = *reinterpret_cast<const float4*>(&Bs[kk][tx * 8 + 4]);
            float af[4] = {a4.x, a4.y, a4.z, a4.w};
            float bf[8] = {b0.x, b0.y, b0.z, b0.w, b1.x, b1.y, b1.z, b1.w};
#pragma unroll
            for (int r = 0; r < 4; r++)
#pragma unroll
                for (int c = 0; c < 8; c++) acc[r][c] = fmaf(af[r], bf[c], acc[r][c]);
        }
        __syncthreads();
    }
#pragma unroll
    for (int r = 0; r < 4; r++) {
        int m = ty * 4 + r;
        float4 v0 = make_float4(acc[r][0], acc[r][1], acc[r][2], acc[r][3]);
        float4 v1 = make_float4(acc[r][4], acc[r][5], acc[r][6], acc[r][7]);
        float* cp = d.C + (size_t)m * d.ldc + n0 + tx * 8;
        *reinterpret_cast<float4*>(cp) = v0;
        *reinterpret_cast<float4*>(cp + 4) = v1;
    }
}

// ---------------- GRU gate combine (sums ksplit4 partials) ----------------
__global__ void k_combine() {
    int idx = blockIdx.x * 256 + threadIdx.x;
    int b = idx >> 10, m = idx & 1023;
    const float* b_ih = g_ptr.w[3];
    const float* b_hh = g_ptr.w[4];
    int o = b * 3072;
    float ir = g_GIE[o + m] + b_ih[m];
    float iz = g_GIE[o + m + 1024] + b_ih[m + 1024];
    float in = g_GIE[o + m + 2048] + b_ih[m + 2048];
    float hr = b_hh[m], hz = b_hh[m + 1024], hn = b_hh[m + 2048];
#pragma unroll
    for (int p = 0; p < 4; p++) {
        ir += g_GI4[p][o + m];        iz += g_GI4[p][o + m + 1024];  in += g_GI4[p][o + m + 2048];
        hr += g_GH4[p][o + m];        hz += g_GH4[p][o + m + 1024];  hn += g_GH4[p][o + m + 2048];
    }
    float r = 1.f / (1.f + expf(-(ir + hr)));
    float z = 1.f / (1.f + expf(-(iz + hz)));
    float n = tanhf(fmaf(r, hn, in));
    float h = g_H[idx];
    g_H[idx] = fmaf(z, h - n, n);
}

// ---------------- gen_s: finalize row i from MS partials, sample all rows ---
__global__ __launch_bounds__(256) void k_gen_s(int i) {
    int b = blockIdx.x & 127;
    int j = blockIdx.x >> 7;
    int e = threadIdx.x << 2;
    uint2 kk = step_key(i);
    size_t off = (size_t)(j * cB + b) * cE + e;
    float4 mu, sg;
    if (j == i) {
        int q = b * 1024 + e;
        float4 bm4 = *reinterpret_cast<const float4*>(g_ptr.w[6] + e);
        float4 bs4 = *reinterpret_cast<const float4*>(g_ptr.w[8] + e);
        mu = bm4; sg = bs4;
#pragma unroll
        for (int p = 0; p < 4; p++) {
            float4 mp = *reinterpret_cast<const float4*>(&g_MSP[p][q]);
            float4 sp = *reinterpret_cast<const float4*>(&g_MSP[p + 4][q]);
            mu.x += mp.x; mu.y += mp.y; mu.z += mp.z; mu.w += mp.w;
            sg.x += sp.x; sg.y += sp.y; sg.z += sp.z; sg.w += sp.w;
        }
        sg.x = softplusf(sg.x); sg.y = softplusf(sg.y);
        sg.z = softplusf(sg.z); sg.w = softplusf(sg.w);
        *reinterpret_cast<float4*>(g_MUS + off) = mu;
        *reinterpret_cast<float4*>(g_SIGS + off) = sg;
    } else {
        mu = *reinterpret_cast<const float4*>(g_MUS + off);
        sg = *reinterpret_cast<const float4*>(g_SIGS + off);
    }
    unsigned p = (unsigned)((b * cT + j) * cE + e);
    float4 s;
    s.x = fmaf(eps_at(kk.x, kk.y, p + 0), sg.x, mu.x);
    s.y = fmaf(eps_at(kk.x, kk.y, p + 1), sg.y, mu.y);
    s.z = fmaf(eps_at(kk.x, kk.y, p + 2), sg.z, mu.z);
    s.w = fmaf(eps_at(kk.x, kk.y, p + 3), sg.w, mu.w);
    *reinterpret_cast<float4*>(g_S + off) = s;
}

// finalize-only (step 127: no attention, but row must be finalized for output)
__global__ __launch_bounds__(256) void k_msfix(int i) {
    int b = blockIdx.x;
    int e = threadIdx.x << 2;
    int q = b * 1024 + e;
    size_t off = (size_t)(i * cB + b) * cE + e;
    float4 mu = *reinterpret_cast<const float4*>(g_ptr.w[6] + e);
    float4 sg = *reinterpret_cast<const float4*>(g_ptr.w[8] + e);
#pragma unroll
    for (int p = 0; p < 4; p++) {
        float4 mp = *reinterpret_cast<const float4*>(&g_MSP[p][q]);
        float4 sp = *reinterpret_cast<const float4*>(&g_MSP[p + 4][q]);
        mu.x += mp.x; mu.y += mp.y; mu.z += mp.z; mu.w += mp.w;
        sg.x += sp.x; sg.y += sp.y; sg.z += sp.z; sg.w += sp.w;
    }
    sg.x = softplusf(sg.x); sg.y = softplusf(sg.y);
    sg.z = softplusf(sg.z); sg.w = softplusf(sg.w);
    *reinterpret_cast<float4*>(g_MUS + off) = mu;
    *reinterpret_cast<float4*>(g_SIGS + off) = sg;
}

// ---------------- mega attention: 2 b's per block, 64 blocks, 512 threads ---
// dyn smem: zu[2*8192] (u then z) + w_s[2048] (scores/weights then ctx) + s_st[2048]
__global__ __launch_bounds__(512) void k_attn(int i) {
    extern __shared__ float sm[];
    float* zu  = sm;            // 16384 floats
    float* w_s = sm + 16384;    // 2048 floats
    float* s_st = sm + 18432;   // 2048 floats (staged s rows, 2 b's)
    int bb = blockIdx.x;        // 0..63
    int nj = i + 1;
    int tid = threadIdx.x;
    int w = tid >> 5, l = tid & 31;

    // load u for 2 b's (4096 float4)
    {
        const float4* src = reinterpret_cast<const float4*>(g_U + (size_t)bb * 16384);
        float4* dst = reinterpret_cast<float4*>(zu);
#pragma unroll
        for (int r = 0; r < 8; r++) dst[tid + r * 512] = src[tid + r * 512];
    }
    __syncthreads();

    // ---- pass 1: scores. 16 warps = 16 (bl,h) combos; s row staged in smem --
    int blw = w >> 3, hw = w & 7;
    const float4* uv4 = reinterpret_cast<const float4*>(zu + blw * 8192 + hw * 1024);
    const float4* sv4 = reinterpret_cast<const float4*>(s_st + blw * 1024);
    for (int j = 0; j < nj; j++) {
        {   // stage 2 rows (512 float4), 1 per thread
            int v = tid;
            int bl = v >> 8, e4 = v & 255;
            reinterpret_cast<float4*>(s_st)[v] =
                reinterpret_cast<const float4*>(g_S + (size_t)(j * cB + bb * 2 + bl) * cE)[e4];
        }
        __syncthreads();
        float acc = 0.f;
#pragma unroll
        for (int k = 0; k < 8; k++) {
            float4 sv = sv4[l + 32 * k];
            float4 uv = uv4[l + 32 * k];
            acc = fmaf(sv.x, uv.x, acc); acc = fmaf(sv.y, uv.y, acc);
            acc = fmaf(sv.z, uv.z, acc); acc = fmaf(sv.w, uv.w, acc);
        }
#pragma unroll
        for (int o = 16; o; o >>= 1) acc += __shfl_xor_sync(0xffffffffu, acc, o);
        if (l == 0) w_s[w * 128 + j] = acc * 0.125f;   // 1/sqrt(64)
        __syncthreads();
    }

    // ---- softmax: combo c = w (16 combos) ----
    {
        float v[4];
#pragma unroll
        for (int cc = 0; cc < 4; cc++) {
            int j = l + 32 * cc;
            v[cc] = (j < nj) ? w_s[w * 128 + j] : -3.0e38f;
        }
        float m = fmaxf(fmaxf(v[0], v[1]), fmaxf(v[2], v[3]));
#pragma unroll
        for (int o = 16; o; o >>= 1) m = fmaxf(m, __shfl_xor_sync(0xffffffffu, m, o));
        float e[4], sum = 0.f;
#pragma unroll
        for (int cc = 0; cc < 4; cc++) {
            int j = l + 32 * cc;
            e[cc] = (j < nj) ? expf(v[cc] - m) : 0.f;
            sum += e[cc];
        }
#pragma unroll
        for (int o = 16; o; o >>= 1) sum += __shfl_xor_sync(0xffffffffu, sum, o);
        float inv = 1.f / sum;
#pragma unroll
        for (int cc = 0; cc < 4; cc++) {
            int j = l + 32 * cc;
            if (j < nj) w_s[w * 128 + j] = e[cc] * inv;
        }
    }
    __syncthreads();

    // ---- pass 2: z[bl][h][e] = sum_j w * s ; thread = (bl, 4 e's) ----
    {
        int bl = tid >> 8;
        int e0 = (tid & 255) << 2;
        int b = bb * 2 + bl;
        float za[8][4];
#pragma unroll
        for (int h = 0; h < 8; h++)
#pragma unroll
            for (int u = 0; u < 4; u++) za[h][u] = 0.f;
        for (int j = 0; j < nj; j++) {
            float4 sv = *reinterpret_cast<const float4*>(g_S + (size_t)(j * cB + b) * cE + e0);
#pragma unroll
            for (int h = 0; h < 8; h++) {
                float wj = w_s[(bl * 8 + h) * 128 + j];
                za[h][0] = fmaf(wj, sv.x, za[h][0]);
                za[h][1] = fmaf(wj, sv.y, za[h][1]);
                za[h][2] = fmaf(wj, sv.z, za[h][2]);
                za[h][3] = fmaf(wj, sv.w, za[h][3]);
            }
        }
        __syncthreads();   // u reads + w_s reads complete
#pragma unroll
        for (int h = 0; h < 8; h++)
            *reinterpret_cast<float4*>(zu + bl * 8192 + h * 1024 + e0) =
                make_float4(za[h][0], za[h][1], za[h][2], za[h][3]);
    }
    __syncthreads();

    // ---- pass 3: ctx[bl][c] = sum_e z[bl][h(c)][e] Wv[e][c] + bv[c] ----
    {
        int bl = tid >> 8;
        int c2 = (tid & 255) << 1;
        int h = c2 >> 6;
        const float* zrow = zu + bl * 8192 + h * 1024;
        const float* Wv = g_ptr.w[13];
        float a0 = 0.f, a1 = 0.f;
        for (int e = 0; e < 1024; e++) {
            float zv = zrow[e];
            float2 wv = *reinterpret_cast<const float2*>(Wv + (size_t)e * 512 + c2);
            a0 = fmaf(zv, wv.x, a0); a1 = fmaf(zv, wv.y, a1);
        }
        float2 bv2 = *reinterpret_cast<const float2*>(g_ptr.w[14] + c2);
        *reinterpret_cast<float2*>(w_s + bl * 512 + c2) =
            make_float2(a0 + bv2.x, a1 + bv2.y);
    }
    __syncthreads();

    // ---- pass 4: X[b, E+e'] = sum_c ctx[bl][c] Wo[c][e'] + bo[e'] ----
    {
        int bl = tid >> 8;
        int e0 = (tid & 255) << 2;
        const float* Wo = g_ptr.w[15];
        float a0 = 0.f, a1 = 0.f, a2 = 0.f, a3 = 0.f;
        for (int c = 0; c < 512; c++) {
            float cv = w_s[bl * 512 + c];
            float4 wo = *reinterpret_cast<const float4*>(Wo + (size_t)c * 1024 + e0);
            a0 = fmaf(cv, wo.x, a0); a1 = fmaf(cv, wo.y, a1);
            a2 = fmaf(cv, wo.z, a2); a3 = fmaf(cv, wo.w, a3);
        }
        float4 bo4 = *reinterpret_cast<const float4*>(g_ptr.w[16] + e0);
        *reinterpret_cast<float4*>(g_X + (bb * 2 + bl) * 2048 + 1024 + e0) =
            make_float4(a0 + bo4.x, a1 + bo4.y, a2 + bo4.z, a3 + bo4.w);
    }
}

// ---------------- final output (B,T,E): step-127 noise ----------------
__global__ __launch_bounds__(256) void k_genout(float* __restrict__ out) {
    int b = blockIdx.x & 127;
    int j = blockIdx.x >> 7;
    int e = threadIdx.x << 2;
    uint2 kk = step_key(cT - 1);
    size_t off = (size_t)(j * cB + b) * cE + e;
    float4 mu = *reinterpret_cast<const float4*>(g_MUS + off);
    float4 sg = *reinterpret_cast<const float4*>(g_SIGS + off);
    unsigned p = (unsigned)((b * cT + j) * cE + e);
    float4 s;
    s.x = fmaf(eps_at(kk.x, kk.y, p + 0), sg.x, mu.x);
    s.y = fmaf(eps_at(kk.x, kk.y, p + 1), sg.y, mu.y);
    s.z = fmaf(eps_at(kk.x, kk.y, p + 2), sg.z, mu.z);
    s.w = fmaf(eps_at(kk.x, kk.y, p + 3), sg.w, mu.w);
    *reinterpret_cast<float4*>(out + p) = s;
}

// ---------------- host side ----------------
extern "C" void kernel_launch(void* const* d_in, const int* in_sizes, int n_in,
                              void* d_out, int out_size) {
    Ptrs P;
    for (int k = 0; k < 17; k++) P.w[k] = (const float*)d_in[k];
    float* out = (float*)d_out;

    constexpr int ATTN_SMEM = (16384 + 2048 + 2048) * 4;   // 81920 B
    cudaFuncSetAttribute(k_attn, cudaFuncAttributeMaxDynamicSharedMemorySize, ATTN_SMEM);

    k_setup<<<1, 1>>>(P);
    k_init<<<1024, 256>>>();
    k_gemm<<<dim3(1, 48, 1), 256>>>(SEL_EB, 0);     // encs half of gi (once)

    for (int i = 0; i < cT; i++) {
        k_gemm<<<dim3(1, 48, 8), 256>>>(SEL_GB, i); // GIC/GH, ksplit4
        k_combine<<<512, 256>>>();
        k_gemm<<<dim3(1, 16, 8), 256>>>(SEL_MS, i); // mu/sig partials, ksplit4

        if (i < cT - 1) {
            k_gen_s<<<(i + 1) * cB, 256>>>(i);      // finalize row i + sample s
            k_gemm<<<dim3(1, 8, 4), 256>>>(SEL_QB, i);   // q partials, ksplit4
            k_gemm<<<dim3(1, 16, 8), 256>>>(SEL_UB, i);  // u per head (sums q)
            k_attn<<<64, 512, ATTN_SMEM>>>(i);      // scores+softmax+z+Wv+Wo
        } else {
            k_msfix<<<cB, 256>>>(i);
        }
    }

    k_genout<<<cT * cB, 256>>>(out);
}

// round 9
// speedup vs baseline: 2.6674x; 1.1505x over previous
#include <cuda_runtime.h>
#include <cstdint>
#include <cmath>

// ---------------- problem constants ----------------
constexpr int cB = 128, cT = 128, cE = 1024, cH = 1024, cNH = 8, cA = 64;
constexpr int cKV = cNH * cA;          // 512
constexpr int BE  = cB * cE;           // 131072

// ---------------- persistent device scratch ----------------
__device__ float g_MUS [cT * BE];          // (T,B,E)
__device__ float g_SIGS[cT * BE];          // (T,B,E)
__device__ float g_S   [cT * BE];          // (T,B,E)
__device__ float g_X   [cB * 2048];        // [encs | context]
__device__ float g_H   [cB * cH];
__device__ float g_GIE [cB * 3072];        // encs @ W_ih[:, :E]^T (once)
__device__ float g_GI8 [8][cB * 3072];     // ctx-half gi partials (ksplit8)
__device__ float g_GH4 [4][cB * 3072];     // gh partials (ksplit4) - written by HMS for NEXT step
__device__ float g_MSP [8][cB * cE];       // mu partials [0..3], sig partials [4..7]
__device__ float g_QP  [4][cB * cKV];      // q partials (ksplit4)
__device__ float g_U   [cB * cNH * cE];    // (b,h,e)

struct Ptrs { const float* w[17]; };
__device__ Ptrs g_ptr;

// ---------------- threefry2x32 (jax-exact) ----------------
__device__ __forceinline__ uint2 tf2x32(unsigned k0, unsigned k1, unsigned x0, unsigned x1) {
    unsigned k2 = k0 ^ k1 ^ 0x1BD11BDAu;
    x0 += k0; x1 += k1;
#define TFR(r) x0 += x1; x1 = __funnelshift_l(x1, x1, r); x1 ^= x0;
    TFR(13) TFR(15) TFR(26) TFR(6)   x0 += k1; x1 += k2 + 1u;
    TFR(17) TFR(29) TFR(16) TFR(24)  x0 += k2; x1 += k0 + 2u;
    TFR(13) TFR(15) TFR(26) TFR(6)   x0 += k0; x1 += k1 + 3u;
    TFR(17) TFR(29) TFR(16) TFR(24)  x0 += k1; x1 += k2 + 4u;
    TFR(13) TFR(15) TFR(26) TFR(6)   x0 += k2; x1 += k0 + 5u;
#undef TFR
    return make_uint2(x0, x1);
}
__device__ __forceinline__ uint2 step_key(int i) { return tf2x32(0u, 1234u, 0u, (unsigned)i); }

// uniform-bits -> N(0,1): jax _uniform + sqrt(2)*erf_inv (XLA Giles poly)
__device__ __forceinline__ float tf_normal(unsigned bits) {
    float f = __uint_as_float((bits >> 9) | 0x3f800000u) - 1.0f;
    float u = fmaf(f, 2.0f, -0.99999994f);
    u = fmaxf(u, -0.99999994f);
    float w = -log1pf(-u * u);
    float p;
    if (w < 5.0f) {
        w -= 2.5f;
        p = 2.81022636e-08f;
        p = fmaf(p, w, 3.43273939e-07f);
        p = fmaf(p, w, -3.5233877e-06f);
        p = fmaf(p, w, -4.39150654e-06f);
        p = fmaf(p, w, 0.00021858087f);
        p = fmaf(p, w, -0.00125372503f);
        p = fmaf(p, w, -0.00417768164f);
        p = fmaf(p, w, 0.246640727f);
        p = fmaf(p, w, 1.50140941f);
    } else {
        w = sqrtf(w) - 3.0f;
        p = -0.000200214257f;
        p = fmaf(p, w, 0.000100950558f);
        p = fmaf(p, w, 0.00134934322f);
        p = fmaf(p, w, -0.00367342844f);
        p = fmaf(p, w, 0.00573950773f);
        p = fmaf(p, w, -0.0076224613f);
        p = fmaf(p, w, 0.00943887047f);
        p = fmaf(p, w, 1.00167406f);
        p = fmaf(p, w, 2.83297682f);
    }
    return 1.4142135623730951f * (p * u);
}
__device__ __forceinline__ float eps_at(unsigned k0, unsigned k1, unsigned idx) {
    uint2 r = tf2x32(k0, k1, 0u, idx);
    return tf_normal(r.x ^ r.y);
}
__device__ __forceinline__ float softplusf(float x) {
    return fmaxf(x, 0.f) + log1pf(expf(-fabsf(x)));
}

// ---------------- setup + init ----------------
__global__ void k_setup(Ptrs p) { g_ptr = p; }
__global__ void k_init() {
    int idx = blockIdx.x * 256 + threadIdx.x;
    const float* encs = g_ptr.w[0];
    if (idx < cB * 2048) {
        int b = idx >> 11, c = idx & 2047;
        g_X[idx] = (c < cE) ? encs[b * cE + c] : 0.f;
    }
    if (idx < cB * cH) g_H[idx] = 0.f;
    if (idx < 4 * cB * 3072) reinterpret_cast<float*>(g_GH4)[idx] = 0.f;  // h0=0 -> gh=0
}

// ---------------- SGEMM: BM=128(all M), BN=64, BK=8, 128 thr, 8x8, dbl-buf --
enum { SEL_EB = 0, SEL_GIC, SEL_HMS, SEL_QB, SEL_UB };

struct GD {
    const float* A; const float* Bm; float* C; const float* qbias;
    int lda, ldb, ldc, K, transB, qsum;
};

__device__ __forceinline__ GD get_desc(int sel, int y, int z, int i) {
    GD d; d.qbias = nullptr; d.transB = 0; d.qsum = 0;
    switch (sel) {
    case SEL_EB:   // encs @ W_ih[:, :E]^T ; N=3072, y in [0,48)
        d.A = g_ptr.w[0]; d.lda = 1024; d.K = 1024;
        d.Bm = g_ptr.w[1] + (size_t)(y * 64) * 2048; d.ldb = 2048; d.transB = 1;
        d.C = g_GIE + y * 64; d.ldc = 3072; break;
    case SEL_GIC:  // ctx @ W_ih[:, E:]^T ; ksplit8 (z), y in [0,48)
        d.A = g_X + 1024 + z * 128; d.lda = 2048; d.K = 128;
        d.Bm = g_ptr.w[1] + 1024 + z * 128 + (size_t)(y * 64) * 2048; d.ldb = 2048; d.transB = 1;
        d.C = g_GI8[z] + y * 64; d.ldc = 3072; break;
    case SEL_HMS:  // h @ [W_hh^T | W_mu | W_sig] ; ksplit4 (z), y in [0,80)
        d.A = g_H + z * 256; d.lda = 1024; d.K = 256;
        if (y < 48) {
            d.Bm = g_ptr.w[2] + z * 256 + (size_t)(y * 64) * 1024; d.ldb = 1024; d.transB = 1;
            d.C = g_GH4[z] + y * 64; d.ldc = 3072;
        } else if (y < 64) {
            int yy = y - 48;
            d.Bm = g_ptr.w[5] + (size_t)(z * 256) * 1024 + yy * 64; d.ldb = 1024;
            d.C = g_MSP[z] + yy * 64; d.ldc = 1024;
        } else {
            int yy = y - 64;
            d.Bm = g_ptr.w[7] + (size_t)(z * 256) * 1024 + yy * 64; d.ldb = 1024;
            d.C = g_MSP[4 + z] + yy * 64; d.ldc = 1024;
        }
        break;
    case SEL_QB:   // s_i @ W_q ; ksplit4 (z), y in [0,8)
        d.A = g_S + (size_t)i * BE + z * 256; d.lda = 1024; d.K = 256;
        d.Bm = g_ptr.w[9] + (size_t)(z * 256) * 512 + y * 64; d.ldb = 512;
        d.C = g_QP[z] + y * 64; d.ldc = 512; break;
    default:       // SEL_UB: u_h = (sum q-partials + b_q) @ W_k_h^T ; z=head, y in [0,16)
        d.qsum = 1;
        d.A = g_QP[0] + z * 64; d.lda = 512; d.K = 64;
        d.qbias = g_ptr.w[10] + z * 64;
        d.Bm = g_ptr.w[11] + z * 64 + (size_t)(y * 64) * 512; d.ldb = 512; d.transB = 1;
        d.C = g_U + z * 1024 + y * 64; d.ldc = 8192; break;
    }
    return d;
}

__global__ __launch_bounds__(128) void k_gemm(int sel, int i) {
    GD d = get_desc(sel, blockIdx.y, blockIdx.z, i);

    __shared__ __align__(16) float As[2][8][132];
    __shared__ __align__(16) float Bs[2][8][68];

    int tid = threadIdx.x;
    int tx = tid & 7, ty = tid >> 3;

    float acc[8][8];
#pragma unroll
    for (int r = 0; r < 8; r++)
#pragma unroll
        for (int c = 0; c < 8; c++) acc[r][c] = 0.f;

    // staging registers
    float4 va[2]; float4 vb;
    int arow = tid >> 1, akc = (tid & 1) << 2;          // A: rows arow, arow+64; k-cols akc..+3
    int bkk = tid >> 4, bnc = (tid & 15) << 2;          // B notrans
    int bnn = tid >> 1, bkc = (tid & 1) << 2;           // B trans

    auto loadA = [&](int k0) {
#pragma unroll
        for (int r = 0; r < 2; r++) {
            const float* ap = d.A + (size_t)(arow + r * 64) * d.lda + k0 + akc;
            if (!d.qsum) {
                va[r] = *reinterpret_cast<const float4*>(ap);
            } else {
                float4 v0 = *reinterpret_cast<const float4*>(ap);
                float4 v1 = *reinterpret_cast<const float4*>(ap + 65536);
                float4 v2 = *reinterpret_cast<const float4*>(ap + 131072);
                float4 v3 = *reinterpret_cast<const float4*>(ap + 196608);
                float4 bb = *reinterpret_cast<const float4*>(d.qbias + k0 + akc);
                va[r].x = v0.x + v1.x + v2.x + v3.x + bb.x;
                va[r].y = v0.y + v1.y + v2.y + v3.y + bb.y;
                va[r].z = v0.z + v1.z + v2.z + v3.z + bb.z;
                va[r].w = v0.w + v1.w + v2.w + v3.w + bb.w;
            }
        }
        if (!d.transB)
            vb = *reinterpret_cast<const float4*>(d.Bm + (size_t)(k0 + bkk) * d.ldb + bnc);
        else
            vb = *reinterpret_cast<const float4*>(d.Bm + (size_t)bnn * d.ldb + k0 + bkc);
    };

    auto storeT = [&](int cur) {
#pragma unroll
        for (int r = 0; r < 2; r++) {
            int row = arow + r * 64;
            As[cur][akc + 0][row] = va[r].x; As[cur][akc + 1][row] = va[r].y;
            As[cur][akc + 2][row] = va[r].z; As[cur][akc + 3][row] = va[r].w;
        }
        if (!d.transB) {
            *reinterpret_cast<float4*>(&Bs[cur][bkk][bnc]) = vb;
        } else {
            Bs[cur][bkc + 0][bnn] = vb.x; Bs[cur][bkc + 1][bnn] = vb.y;
            Bs[cur][bkc + 2][bnn] = vb.z; Bs[cur][bkc + 3][bnn] = vb.w;
        }
    };

    int nt = d.K >> 3;
    loadA(0);
    int cur = 0;
    for (int t = 0; t < nt; t++) {
        storeT(cur);
        __syncthreads();
        if (t + 1 < nt) loadA((t + 1) << 3);
#pragma unroll
        for (int kk = 0; kk < 8; kk++) {
            float4 a0 = *reinterpret_cast<const float4*>(&As[cur][kk][ty * 8]);
            float4 a1 = *reinterpret_cast<const float4*>(&As[cur][kk][ty * 8 + 4]);
            float4 b0 = *reinterpret_cast<const float4*>(&Bs[cur][kk][tx * 8]);
            float4 b1 = *reinterpret_cast<const float4*>(&Bs[cur][kk][tx * 8 + 4]);
            float af[8] = {a0.x, a0.y, a0.z, a0.w, a1.x, a1.y, a1.z, a1.w};
            float bf[8] = {b0.x, b0.y, b0.z, b0.w, b1.x, b1.y, b1.z, b1.w};
#pragma unroll
            for (int r = 0; r < 8; r++)
#pragma unroll
                for (int c = 0; c < 8; c++) acc[r][c] = fmaf(af[r], bf[c], acc[r][c]);
        }
        cur ^= 1;
    }

#pragma unroll
    for (int r = 0; r < 8; r++) {
        int m = ty * 8 + r;
        float* cp = d.C + (size_t)m * d.ldc + tx * 8;
        *reinterpret_cast<float4*>(cp)     = make_float4(acc[r][0], acc[r][1], acc[r][2], acc[r][3]);
        *reinterpret_cast<float4*>(cp + 4) = make_float4(acc[r][4], acc[r][5], acc[r][6], acc[r][7]);
    }
}

// ---------------- GRU gate combine (sums GI8 x8 + GH4 x4 partials) ---------
__global__ void k_combine() {
    int idx = blockIdx.x * 256 + threadIdx.x;
    int b = idx >> 10, m = idx & 1023;
    const float* b_ih = g_ptr.w[3];
    const float* b_hh = g_ptr.w[4];
    int o = b * 3072;
    float ir = g_GIE[o + m] + b_ih[m];
    float iz = g_GIE[o + m + 1024] + b_ih[m + 1024];
    float in = g_GIE[o + m + 2048] + b_ih[m + 2048];
#pragma unroll
    for (int p = 0; p < 8; p++) {
        ir += g_GI8[p][o + m];
        iz += g_GI8[p][o + m + 1024];
        in += g_GI8[p][o + m + 2048];
    }
    float hr = b_hh[m], hz = b_hh[m + 1024], hn = b_hh[m + 2048];
#pragma unroll
    for (int p = 0; p < 4; p++) {
        hr += g_GH4[p][o + m];
        hz += g_GH4[p][o + m + 1024];
        hn += g_GH4[p][o + m + 2048];
    }
    float r = 1.f / (1.f + expf(-(ir + hr)));
    float z = 1.f / (1.f + expf(-(iz + hz)));
    float n = tanhf(fmaf(r, hn, in));
    float h = g_H[idx];
    g_H[idx] = fmaf(z, h - n, n);
}

// ---------------- gen_s: finalize row i from MS partials, sample all rows ---
__global__ __launch_bounds__(256) void k_gen_s(int i) {
    int b = blockIdx.x & 127;
    int j = blockIdx.x >> 7;
    int e = threadIdx.x << 2;
    uint2 kk = step_key(i);
    size_t off = (size_t)(j * cB + b) * cE + e;
    float4 mu, sg;
    if (j == i) {
        int q = b * 1024 + e;
        mu = *reinterpret_cast<const float4*>(g_ptr.w[6] + e);
        sg = *reinterpret_cast<const float4*>(g_ptr.w[8] + e);
#pragma unroll
        for (int p = 0; p < 4; p++) {
            float4 mp = *reinterpret_cast<const float4*>(&g_MSP[p][q]);
            float4 sp = *reinterpret_cast<const float4*>(&g_MSP[p + 4][q]);
            mu.x += mp.x; mu.y += mp.y; mu.z += mp.z; mu.w += mp.w;
            sg.x += sp.x; sg.y += sp.y; sg.z += sp.z; sg.w += sp.w;
        }
        sg.x = softplusf(sg.x); sg.y = softplusf(sg.y);
        sg.z = softplusf(sg.z); sg.w = softplusf(sg.w);
        *reinterpret_cast<float4*>(g_MUS + off) = mu;
        *reinterpret_cast<float4*>(g_SIGS + off) = sg;
    } else {
        mu = *reinterpret_cast<const float4*>(g_MUS + off);
        sg = *reinterpret_cast<const float4*>(g_SIGS + off);
    }
    unsigned p = (unsigned)((b * cT + j) * cE + e);
    float4 s;
    s.x = fmaf(eps_at(kk.x, kk.y, p + 0), sg.x, mu.x);
    s.y = fmaf(eps_at(kk.x, kk.y, p + 1), sg.y, mu.y);
    s.z = fmaf(eps_at(kk.x, kk.y, p + 2), sg.z, mu.z);
    s.w = fmaf(eps_at(kk.x, kk.y, p + 3), sg.w, mu.w);
    *reinterpret_cast<float4*>(g_S + off) = s;
}

// finalize-only (step 127)
__global__ __launch_bounds__(256) void k_msfix(int i) {
    int b = blockIdx.x;
    int e = threadIdx.x << 2;
    int q = b * 1024 + e;
    size_t off = (size_t)(i * cB + b) * cE + e;
    float4 mu = *reinterpret_cast<const float4*>(g_ptr.w[6] + e);
    float4 sg = *reinterpret_cast<const float4*>(g_ptr.w[8] + e);
#pragma unroll
    for (int p = 0; p < 4; p++) {
        float4 mp = *reinterpret_cast<const float4*>(&g_MSP[p][q]);
        float4 sp = *reinterpret_cast<const float4*>(&g_MSP[p + 4][q]);
        mu.x += mp.x; mu.y += mp.y; mu.z += mp.z; mu.w += mp.w;
        sg.x += sp.x; sg.y += sp.y; sg.z += sp.z; sg.w += sp.w;
    }
    sg.x = softplusf(sg.x); sg.y = softplusf(sg.y);
    sg.z = softplusf(sg.z); sg.w = softplusf(sg.w);
    *reinterpret_cast<float4*>(g_MUS + off) = mu;
    *reinterpret_cast<float4*>(g_SIGS + off) = sg;
}

// ---------------- mega attention: 2 b's per block, 64 blocks, 512 threads ---
__global__ __launch_bounds__(512) void k_attn(int i) {
    extern __shared__ float sm[];
    float* zu  = sm;            // 16384 floats
    float* w_s = sm + 16384;    // 2048 floats
    float* s_st = sm + 18432;   // 2048 floats
    int bb = blockIdx.x;
    int nj = i + 1;
    int tid = threadIdx.x;
    int w = tid >> 5, l = tid & 31;

    {
        const float4* src = reinterpret_cast<const float4*>(g_U + (size_t)bb * 16384);
        float4* dst = reinterpret_cast<float4*>(zu);
#pragma unroll
        for (int r = 0; r < 8; r++) dst[tid + r * 512] = src[tid + r * 512];
    }
    __syncthreads();

    int blw = w >> 3, hw = w & 7;
    const float4* uv4 = reinterpret_cast<const float4*>(zu + blw * 8192 + hw * 1024);
    const float4* sv4 = reinterpret_cast<const float4*>(s_st + blw * 1024);
    for (int j = 0; j < nj; j++) {
        {
            int bl = tid >> 8, e4 = tid & 255;
            reinterpret_cast<float4*>(s_st)[tid] =
                reinterpret_cast<const float4*>(g_S + (size_t)(j * cB + bb * 2 + bl) * cE)[e4];
        }
        __syncthreads();
        float acc = 0.f;
#pragma unroll
        for (int k = 0; k < 8; k++) {
            float4 sv = sv4[l + 32 * k];
            float4 uv = uv4[l + 32 * k];
            acc = fmaf(sv.x, uv.x, acc); acc = fmaf(sv.y, uv.y, acc);
            acc = fmaf(sv.z, uv.z, acc); acc = fmaf(sv.w, uv.w, acc);
        }
#pragma unroll
        for (int o = 16; o; o >>= 1) acc += __shfl_xor_sync(0xffffffffu, acc, o);
        if (l == 0) w_s[w * 128 + j] = acc * 0.125f;
        __syncthreads();
    }

    {
        float v[4];
#pragma unroll
        for (int cc = 0; cc < 4; cc++) {
            int j = l + 32 * cc;
            v[cc] = (j < nj) ? w_s[w * 128 + j] : -3.0e38f;
        }
        float m = fmaxf(fmaxf(v[0], v[1]), fmaxf(v[2], v[3]));
#pragma unroll
        for (int o = 16; o; o >>= 1) m = fmaxf(m, __shfl_xor_sync(0xffffffffu, m, o));
        float e[4], sum = 0.f;
#pragma unroll
        for (int cc = 0; cc < 4; cc++) {
            int j = l + 32 * cc;
            e[cc] = (j < nj) ? expf(v[cc] - m) : 0.f;
            sum += e[cc];
        }
#pragma unroll
        for (int o = 16; o; o >>= 1) sum += __shfl_xor_sync(0xffffffffu, sum, o);
        float inv = 1.f / sum;
#pragma unroll
        for (int cc = 0; cc < 4; cc++) {
            int j = l + 32 * cc;
            if (j < nj) w_s[w * 128 + j] = e[cc] * inv;
        }
    }
    __syncthreads();

    {
        int bl = tid >> 8;
        int e0 = (tid & 255) << 2;
        int b = bb * 2 + bl;
        float za[8][4];
#pragma unroll
        for (int h = 0; h < 8; h++)
#pragma unroll
            for (int u = 0; u < 4; u++) za[h][u] = 0.f;
        for (int j = 0; j < nj; j++) {
            float4 sv = *reinterpret_cast<const float4*>(g_S + (size_t)(j * cB + b) * cE + e0);
#pragma unroll
            for (int h = 0; h < 8; h++) {
                float wj = w_s[(bl * 8 + h) * 128 + j];
                za[h][0] = fmaf(wj, sv.x, za[h][0]);
                za[h][1] = fmaf(wj, sv.y, za[h][1]);
                za[h][2] = fmaf(wj, sv.z, za[h][2]);
                za[h][3] = fmaf(wj, sv.w, za[h][3]);
            }
        }
        __syncthreads();
#pragma unroll
        for (int h = 0; h < 8; h++)
            *reinterpret_cast<float4*>(zu + bl * 8192 + h * 1024 + e0) =
                make_float4(za[h][0], za[h][1], za[h][2], za[h][3]);
    }
    __syncthreads();

    {
        int bl = tid >> 8;
        int c2 = (tid & 255) << 1;
        int h = c2 >> 6;
        const float* zrow = zu + bl * 8192 + h * 1024;
        const float* Wv = g_ptr.w[13];
        float a0 = 0.f, a1 = 0.f;
        for (int e = 0; e < 1024; e++) {
            float zv = zrow[e];
            float2 wv = *reinterpret_cast<const float2*>(Wv + (size_t)e * 512 + c2);
            a0 = fmaf(zv, wv.x, a0); a1 = fmaf(zv, wv.y, a1);
        }
        float2 bv2 = *reinterpret_cast<const float2*>(g_ptr.w[14] + c2);
        *reinterpret_cast<float2*>(w_s + bl * 512 + c2) = make_float2(a0 + bv2.x, a1 + bv2.y);
    }
    __syncthreads();

    {
        int bl = tid >> 8;
        int e0 = (tid & 255) << 2;
        const float* Wo = g_ptr.w[15];
        float a0 = 0.f, a1 = 0.f, a2 = 0.f, a3 = 0.f;
        for (int c = 0; c < 512; c++) {
            float cv = w_s[bl * 512 + c];
            float4 wo = *reinterpret_cast<const float4*>(Wo + (size_t)c * 1024 + e0);
            a0 = fmaf(cv, wo.x, a0); a1 = fmaf(cv, wo.y, a1);
            a2 = fmaf(cv, wo.z, a2); a3 = fmaf(cv, wo.w, a3);
        }
        float4 bo4 = *reinterpret_cast<const float4*>(g_ptr.w[16] + e0);
        *reinterpret_cast<float4*>(g_X + (bb * 2 + bl) * 2048 + 1024 + e0) =
            make_float4(a0 + bo4.x, a1 + bo4.y, a2 + bo4.z, a3 + bo4.w);
    }
}

// ---------------- final output (B,T,E): step-127 noise ----------------
__global__ __launch_bounds__(256) void k_genout(float* __restrict__ out) {
    int b = blockIdx.x & 127;
    int j = blockIdx.x >> 7;
    int e = threadIdx.x << 2;
    uint2 kk = step_key(cT - 1);
    size_t off = (size_t)(j * cB + b) * cE + e;
    float4 mu = *reinterpret_cast<const float4*>(g_MUS + off);
    float4 sg = *reinterpret_cast<const float4*>(g_SIGS + off);
    unsigned p = (unsigned)((b * cT + j) * cE + e);
    float4 s;
    s.x = fmaf(eps_at(kk.x, kk.y, p + 0), sg.x, mu.x);
    s.y = fmaf(eps_at(kk.x, kk.y, p + 1), sg.y, mu.y);
    s.z = fmaf(eps_at(kk.x, kk.y, p + 2), sg.z, mu.z);
    s.w = fmaf(eps_at(kk.x, kk.y, p + 3), sg.w, mu.w);
    *reinterpret_cast<float4*>(out + p) = s;
}

// ---------------- host side ----------------
extern "C" void kernel_launch(void* const* d_in, const int* in_sizes, int n_in,
                              void* d_out, int out_size) {
    Ptrs P;
    for (int k = 0; k < 17; k++) P.w[k] = (const float*)d_in[k];
    float* out = (float*)d_out;

    constexpr int ATTN_SMEM = (16384 + 2048 + 2048) * 4;   // 81920 B
    cudaFuncSetAttribute(k_attn, cudaFuncAttributeMaxDynamicSharedMemorySize, ATTN_SMEM);

    k_setup<<<1, 1>>>(P);
    k_init<<<6144, 256>>>();
    k_gemm<<<dim3(1, 48, 1), 128>>>(SEL_EB, 0);      // encs half of gi (once)

    for (int i = 0; i < cT; i++) {
        k_gemm<<<dim3(1, 48, 8), 128>>>(SEL_GIC, i); // ctx-half gi, ksplit8
        k_combine<<<512, 256>>>();                   // h update (uses prev GH4)
        k_gemm<<<dim3(1, 80, 4), 128>>>(SEL_HMS, i); // h@[W_hh|W_mu|W_sig]

        if (i < cT - 1) {
            k_gen_s<<<(i + 1) * cB, 256>>>(i);       // finalize mu/sig row i + sample S
            k_gemm<<<dim3(1, 8, 4), 128>>>(SEL_QB, i);
            k_gemm<<<dim3(1, 16, 8), 128>>>(SEL_UB, i);
            k_attn<<<64, 512, ATTN_SMEM>>>(i);
        } else {
            k_msfix<<<cB, 256>>>(i);
        }
    }

    k_genout<<<cT * cB, 256>>>(out);
}

// round 10
// speedup vs baseline: 2.9448x; 1.1040x over previous
#include <cuda_runtime.h>
#include <cstdint>
#include <cmath>

// ---------------- problem constants ----------------
constexpr int cB = 128, cT = 128, cE = 1024, cH = 1024, cNH = 8, cA = 64;
constexpr int cKV = cNH * cA;          // 512
constexpr int BE  = cB * cE;           // 131072

// ---------------- persistent device scratch ----------------
__device__ float g_MUS [cT * BE];          // (T,B,E)
__device__ float g_SIGS[cT * BE];          // (T,B,E)
__device__ float g_S   [cT * BE];          // (T,B,E)
__device__ float g_X   [cB * 2048];        // [encs | context]
__device__ float g_H   [cB * cH];
__device__ float g_GIE [cB * 3072];        // encs @ W_ih[:, :E]^T (once)
__device__ float g_GI8 [8][cB * 3072];     // ctx-half gi partials (ksplit8)
__device__ float g_GH4 [4][cB * 3072];     // gh partials (ksplit4)
__device__ float g_MSP [8][cB * cE];       // mu partials [0..3], sig partials [4..7]
__device__ float g_QP  [8][cB * cKV];      // q partials (ksplit8)
__device__ float g_U   [cB * cNH * cE];    // (b,h,e)

struct Ptrs { const float* w[17]; };
__device__ Ptrs g_ptr;

// ---------------- threefry2x32 (jax-exact) ----------------
__device__ __forceinline__ uint2 tf2x32(unsigned k0, unsigned k1, unsigned x0, unsigned x1) {
    unsigned k2 = k0 ^ k1 ^ 0x1BD11BDAu;
    x0 += k0; x1 += k1;
#define TFR(r) x0 += x1; x1 = __funnelshift_l(x1, x1, r); x1 ^= x0;
    TFR(13) TFR(15) TFR(26) TFR(6)   x0 += k1; x1 += k2 + 1u;
    TFR(17) TFR(29) TFR(16) TFR(24)  x0 += k2; x1 += k0 + 2u;
    TFR(13) TFR(15) TFR(26) TFR(6)   x0 += k0; x1 += k1 + 3u;
    TFR(17) TFR(29) TFR(16) TFR(24)  x0 += k1; x1 += k2 + 4u;
    TFR(13) TFR(15) TFR(26) TFR(6)   x0 += k2; x1 += k0 + 5u;
#undef TFR
    return make_uint2(x0, x1);
}
__device__ __forceinline__ uint2 step_key(int i) { return tf2x32(0u, 1234u, 0u, (unsigned)i); }

// uniform-bits -> N(0,1): jax _uniform + sqrt(2)*erf_inv (XLA Giles poly)
__device__ __forceinline__ float tf_normal(unsigned bits) {
    float f = __uint_as_float((bits >> 9) | 0x3f800000u) - 1.0f;
    float u = fmaf(f, 2.0f, -0.99999994f);
    u = fmaxf(u, -0.99999994f);
    float w = -log1pf(-u * u);
    float p;
    if (w < 5.0f) {
        w -= 2.5f;
        p = 2.81022636e-08f;
        p = fmaf(p, w, 3.43273939e-07f);
        p = fmaf(p, w, -3.5233877e-06f);
        p = fmaf(p, w, -4.39150654e-06f);
        p = fmaf(p, w, 0.00021858087f);
        p = fmaf(p, w, -0.00125372503f);
        p = fmaf(p, w, -0.00417768164f);
        p = fmaf(p, w, 0.246640727f);
        p = fmaf(p, w, 1.50140941f);
    } else {
        w = sqrtf(w) - 3.0f;
        p = -0.000200214257f;
        p = fmaf(p, w, 0.000100950558f);
        p = fmaf(p, w, 0.00134934322f);
        p = fmaf(p, w, -0.00367342844f);
        p = fmaf(p, w, 0.00573950773f);
        p = fmaf(p, w, -0.0076224613f);
        p = fmaf(p, w, 0.00943887047f);
        p = fmaf(p, w, 1.00167406f);
        p = fmaf(p, w, 2.83297682f);
    }
    return 1.4142135623730951f * (p * u);
}
__device__ __forceinline__ float eps_at(unsigned k0, unsigned k1, unsigned idx) {
    uint2 r = tf2x32(k0, k1, 0u, idx);
    return tf_normal(r.x ^ r.y);
}
__device__ __forceinline__ float softplusf(float x) {
    return fmaxf(x, 0.f) + log1pf(expf(-fabsf(x)));
}

// ---------------- setup + init ----------------
__global__ void k_setup(Ptrs p) { g_ptr = p; }
__global__ void k_init() {
    int idx = blockIdx.x * 256 + threadIdx.x;
    const float* encs = g_ptr.w[0];
    if (idx < cB * 2048) {
        int b = idx >> 11, c = idx & 2047;
        g_X[idx] = (c < cE) ? encs[b * cE + c] : 0.f;
    }
    if (idx < cB * cH) g_H[idx] = 0.f;
    if (idx < 4 * cB * 3072) reinterpret_cast<float*>(g_GH4)[idx] = 0.f;  // h0=0 -> gh=0
}

// ---- SGEMM: BM=128(all M), BN=128, BK=8, 256 thr, 8x8 microtile, dbl-buf ---
enum { SEL_EB = 0, SEL_GIC, SEL_HMS, SEL_QB, SEL_UB };

struct GD {
    const float* A; const float* Bm; float* C; const float* qbias;
    int lda, ldb, ldc, K, transB, qsum;
};

__device__ __forceinline__ GD get_desc(int sel, int y, int z, int i) {
    GD d; d.qbias = nullptr; d.transB = 0; d.qsum = 0;
    switch (sel) {
    case SEL_EB:   // encs @ W_ih[:, :E]^T ; y in [0,24)
        d.A = g_ptr.w[0]; d.lda = 1024; d.K = 1024;
        d.Bm = g_ptr.w[1] + (size_t)(y * 128) * 2048; d.ldb = 2048; d.transB = 1;
        d.C = g_GIE + y * 128; d.ldc = 3072; break;
    case SEL_GIC:  // ctx @ W_ih[:, E:]^T ; ksplit8 (z), y in [0,24)
        d.A = g_X + 1024 + z * 128; d.lda = 2048; d.K = 128;
        d.Bm = g_ptr.w[1] + 1024 + z * 128 + (size_t)(y * 128) * 2048; d.ldb = 2048; d.transB = 1;
        d.C = g_GI8[z] + y * 128; d.ldc = 3072; break;
    case SEL_HMS:  // h @ [W_hh^T | W_mu | W_sig] ; ksplit4 (z), y in [0,40)
        d.A = g_H + z * 256; d.lda = 1024; d.K = 256;
        if (y < 24) {
            d.Bm = g_ptr.w[2] + z * 256 + (size_t)(y * 128) * 1024; d.ldb = 1024; d.transB = 1;
            d.C = g_GH4[z] + y * 128; d.ldc = 3072;
        } else if (y < 32) {
            int yy = y - 24;
            d.Bm = g_ptr.w[5] + (size_t)(z * 256) * 1024 + yy * 128; d.ldb = 1024;
            d.C = g_MSP[z] + yy * 128; d.ldc = 1024;
        } else {
            int yy = y - 32;
            d.Bm = g_ptr.w[7] + (size_t)(z * 256) * 1024 + yy * 128; d.ldb = 1024;
            d.C = g_MSP[4 + z] + yy * 128; d.ldc = 1024;
        }
        break;
    case SEL_QB:   // s_i @ W_q ; ksplit8 (z), y in [0,4)
        d.A = g_S + (size_t)i * BE + z * 128; d.lda = 1024; d.K = 128;
        d.Bm = g_ptr.w[9] + (size_t)(z * 128) * 512 + y * 128; d.ldb = 512;
        d.C = g_QP[z] + y * 128; d.ldc = 512; break;
    default:       // SEL_UB: u_h = (sum 8 q-partials + b_q) @ W_k_h^T ; z=head, y in [0,8)
        d.qsum = 1;
        d.A = g_QP[0] + z * 64; d.lda = 512; d.K = 64;
        d.qbias = g_ptr.w[10] + z * 64;
        d.Bm = g_ptr.w[11] + z * 64 + (size_t)(y * 128) * 512; d.ldb = 512; d.transB = 1;
        d.C = g_U + z * 1024 + y * 128; d.ldc = 8192; break;
    }
    return d;
}

__global__ __launch_bounds__(256) void k_gemm(int sel, int i) {
    GD d = get_desc(sel, blockIdx.y, blockIdx.z, i);

    __shared__ __align__(16) float As[2][8][132];
    __shared__ __align__(16) float Bs[2][8][132];

    int tid = threadIdx.x;
    int tx = tid & 15, ty = tid >> 4;

    float acc[8][8];
#pragma unroll
    for (int r = 0; r < 8; r++)
#pragma unroll
        for (int c = 0; c < 8; c++) acc[r][c] = 0.f;

    // staging registers (1 float4 A, 1 float4 B per thread)
    float4 va, vb;
    int arow = tid >> 1, akc = (tid & 1) << 2;        // A rows 0..127, k 0/4
    int bkk = tid >> 5, bnc = (tid & 31) << 2;        // B notrans: k row, n col
    int bnn = tid >> 1, bkc = (tid & 1) << 2;         // B trans: n row, k col

    auto loadT = [&](int k0) {
        const float* ap = d.A + (size_t)arow * d.lda + k0 + akc;
        if (!d.qsum) {
            va = *reinterpret_cast<const float4*>(ap);
        } else {
            va = *reinterpret_cast<const float4*>(d.qbias + k0 + akc);
#pragma unroll
            for (int p = 0; p < 8; p++) {
                float4 v = *reinterpret_cast<const float4*>(ap + p * 65536);
                va.x += v.x; va.y += v.y; va.z += v.z; va.w += v.w;
            }
        }
        if (!d.transB)
            vb = *reinterpret_cast<const float4*>(d.Bm + (size_t)(k0 + bkk) * d.ldb + bnc);
        else
            vb = *reinterpret_cast<const float4*>(d.Bm + (size_t)bnn * d.ldb + k0 + bkc);
    };
    auto storeT = [&](int cur) {
        As[cur][akc + 0][arow] = va.x; As[cur][akc + 1][arow] = va.y;
        As[cur][akc + 2][arow] = va.z; As[cur][akc + 3][arow] = va.w;
        if (!d.transB) {
            *reinterpret_cast<float4*>(&Bs[cur][bkk][bnc]) = vb;
        } else {
            Bs[cur][bkc + 0][bnn] = vb.x; Bs[cur][bkc + 1][bnn] = vb.y;
            Bs[cur][bkc + 2][bnn] = vb.z; Bs[cur][bkc + 3][bnn] = vb.w;
        }
    };

    int nt = d.K >> 3;
    loadT(0);
    int cur = 0;
    for (int t = 0; t < nt; t++) {
        storeT(cur);
        __syncthreads();
        if (t + 1 < nt) loadT((t + 1) << 3);
#pragma unroll
        for (int kk = 0; kk < 8; kk++) {
            float4 a0 = *reinterpret_cast<const float4*>(&As[cur][kk][ty * 8]);
            float4 a1 = *reinterpret_cast<const float4*>(&As[cur][kk][ty * 8 + 4]);
            float4 b0 = *reinterpret_cast<const float4*>(&Bs[cur][kk][tx * 8]);
            float4 b1 = *reinterpret_cast<const float4*>(&Bs[cur][kk][tx * 8 + 4]);
            float af[8] = {a0.x, a0.y, a0.z, a0.w, a1.x, a1.y, a1.z, a1.w};
            float bf[8] = {b0.x, b0.y, b0.z, b0.w, b1.x, b1.y, b1.z, b1.w};
#pragma unroll
            for (int r = 0; r < 8; r++)
#pragma unroll
                for (int c = 0; c < 8; c++) acc[r][c] = fmaf(af[r], bf[c], acc[r][c]);
        }
        __syncthreads();
        cur ^= 1;
    }

#pragma unroll
    for (int r = 0; r < 8; r++) {
        int m = ty * 8 + r;
        float* cp = d.C + (size_t)m * d.ldc + tx * 8;
        *reinterpret_cast<float4*>(cp)     = make_float4(acc[r][0], acc[r][1], acc[r][2], acc[r][3]);
        *reinterpret_cast<float4*>(cp + 4) = make_float4(acc[r][4], acc[r][5], acc[r][6], acc[r][7]);
    }
}

// ---------------- GRU gate combine (sums GI8 x8 + GH4 x4 partials) ---------
__global__ void k_combine() {
    int idx = blockIdx.x * 256 + threadIdx.x;
    int b = idx >> 10, m = idx & 1023;
    const float* b_ih = g_ptr.w[3];
    const float* b_hh = g_ptr.w[4];
    int o = b * 3072;
    float ir = g_GIE[o + m] + b_ih[m];
    float iz = g_GIE[o + m + 1024] + b_ih[m + 1024];
    float in = g_GIE[o + m + 2048] + b_ih[m + 2048];
#pragma unroll
    for (int p = 0; p < 8; p++) {
        ir += g_GI8[p][o + m];
        iz += g_GI8[p][o + m + 1024];
        in += g_GI8[p][o + m + 2048];
    }
    float hr = b_hh[m], hz = b_hh[m + 1024], hn = b_hh[m + 2048];
#pragma unroll
    for (int p = 0; p < 4; p++) {
        hr += g_GH4[p][o + m];
        hz += g_GH4[p][o + m + 1024];
        hn += g_GH4[p][o + m + 2048];
    }
    float r = 1.f / (1.f + expf(-(ir + hr)));
    float z = 1.f / (1.f + expf(-(iz + hz)));
    float n = tanhf(fmaf(r, hn, in));
    float h = g_H[idx];
    g_H[idx] = fmaf(z, h - n, n);
}

// ---------------- gen_s: finalize row i from MS partials, sample all rows ---
__global__ __launch_bounds__(256) void k_gen_s(int i) {
    int b = blockIdx.x & 127;
    int j = blockIdx.x >> 7;
    int e = threadIdx.x << 2;
    uint2 kk = step_key(i);
    size_t off = (size_t)(j * cB + b) * cE + e;
    float4 mu, sg;
    if (j == i) {
        int q = b * 1024 + e;
        mu = *reinterpret_cast<const float4*>(g_ptr.w[6] + e);
        sg = *reinterpret_cast<const float4*>(g_ptr.w[8] + e);
#pragma unroll
        for (int p = 0; p < 4; p++) {
            float4 mp = *reinterpret_cast<const float4*>(&g_MSP[p][q]);
            float4 sp = *reinterpret_cast<const float4*>(&g_MSP[p + 4][q]);
            mu.x += mp.x; mu.y += mp.y; mu.z += mp.z; mu.w += mp.w;
            sg.x += sp.x; sg.y += sp.y; sg.z += sp.z; sg.w += sp.w;
        }
        sg.x = softplusf(sg.x); sg.y = softplusf(sg.y);
        sg.z = softplusf(sg.z); sg.w = softplusf(sg.w);
        *reinterpret_cast<float4*>(g_MUS + off) = mu;
        *reinterpret_cast<float4*>(g_SIGS + off) = sg;
    } else {
        mu = *reinterpret_cast<const float4*>(g_MUS + off);
        sg = *reinterpret_cast<const float4*>(g_SIGS + off);
    }
    unsigned p = (unsigned)((b * cT + j) * cE + e);
    float4 s;
    s.x = fmaf(eps_at(kk.x, kk.y, p + 0), sg.x, mu.x);
    s.y = fmaf(eps_at(kk.x, kk.y, p + 1), sg.y, mu.y);
    s.z = fmaf(eps_at(kk.x, kk.y, p + 2), sg.z, mu.z);
    s.w = fmaf(eps_at(kk.x, kk.y, p + 3), sg.w, mu.w);
    *reinterpret_cast<float4*>(g_S + off) = s;
}

// finalize-only (step 127)
__global__ __launch_bounds__(256) void k_msfix(int i) {
    int b = blockIdx.x;
    int e = threadIdx.x << 2;
    int q = b * 1024 + e;
    size_t off = (size_t)(i * cB + b) * cE + e;
    float4 mu = *reinterpret_cast<const float4*>(g_ptr.w[6] + e);
    float4 sg = *reinterpret_cast<const float4*>(g_ptr.w[8] + e);
#pragma unroll
    for (int p = 0; p < 4; p++) {
        float4 mp = *reinterpret_cast<const float4*>(&g_MSP[p][q]);
        float4 sp = *reinterpret_cast<const float4*>(&g_MSP[p + 4][q]);
        mu.x += mp.x; mu.y += mp.y; mu.z += mp.z; mu.w += mp.w;
        sg.x += sp.x; sg.y += sp.y; sg.z += sp.z; sg.w += sp.w;
    }
    sg.x = softplusf(sg.x); sg.y = softplusf(sg.y);
    sg.z = softplusf(sg.z); sg.w = softplusf(sg.w);
    *reinterpret_cast<float4*>(g_MUS + off) = mu;
    *reinterpret_cast<float4*>(g_SIGS + off) = sg;
}

// ---------------- mega attention: 2 b's per block, 64 blocks, 512 threads ---
// smem: z[16384] + w_s[2048] + s_st[8192] (4 j-rows x 2 b staged per round)
__global__ __launch_bounds__(512) void k_attn(int i) {
    extern __shared__ float sm[];
    float* zs  = sm;            // 16384 floats (z, pass2+)
    float* w_s = sm + 16384;    // 2048 floats
    float* s_st = sm + 18432;   // 8192 floats: [bl][jr][1024]
    int bb = blockIdx.x;
    int nj = i + 1;
    int tid = threadIdx.x;
    int w = tid >> 5, l = tid & 31;
    int blw = w >> 3, hw = w & 7;

    // ---- pass 1: scores; u held in registers, 4 j-rows staged per round ----
    {
        float4 ureg[8];
        const float4* up = reinterpret_cast<const float4*>(
            g_U + (size_t)(bb * 2 + blw) * 8192 + hw * 1024);
#pragma unroll
        for (int k = 0; k < 8; k++) ureg[k] = up[l + 32 * k];

        for (int j0 = 0; j0 < nj; j0 += 4) {
#pragma unroll
            for (int r = 0; r < 4; r++) {
                int idx = tid + r * 512;          // 0..2047 float4
                int row = idx >> 8;               // 0..7 = bl*4 + jr
                int bl = row >> 2, jr = row & 3;
                int j = j0 + jr;
                if (j < nj)
                    reinterpret_cast<float4*>(s_st)[idx] =
                        reinterpret_cast<const float4*>(
                            g_S + (size_t)(j * cB + bb * 2 + bl) * cE)[idx & 255];
            }
            __syncthreads();
            const float4* sbase = reinterpret_cast<const float4*>(s_st + blw * 4096);
#pragma unroll
            for (int jr = 0; jr < 4; jr++) {
                int j = j0 + jr;
                if (j < nj) {
                    const float4* sv4 = sbase + jr * 256;
                    float acc = 0.f;
#pragma unroll
                    for (int k = 0; k < 8; k++) {
                        float4 sv = sv4[l + 32 * k];
                        acc = fmaf(sv.x, ureg[k].x, acc); acc = fmaf(sv.y, ureg[k].y, acc);
                        acc = fmaf(sv.z, ureg[k].z, acc); acc = fmaf(sv.w, ureg[k].w, acc);
                    }
#pragma unroll
                    for (int o = 16; o; o >>= 1) acc += __shfl_xor_sync(0xffffffffu, acc, o);
                    if (l == 0) w_s[w * 128 + j] = acc * 0.125f;   // 1/sqrt(64)
                }
            }
            __syncthreads();
        }
    }

    // ---- softmax per (bl,h) combo = warp ----
    {
        float v[4];
#pragma unroll
        for (int cc = 0; cc < 4; cc++) {
            int j = l + 32 * cc;
            v[cc] = (j < nj) ? w_s[w * 128 + j] : -3.0e38f;
        }
        float m = fmaxf(fmaxf(v[0], v[1]), fmaxf(v[2], v[3]));
#pragma unroll
        for (int o = 16; o; o >>= 1) m = fmaxf(m, __shfl_xor_sync(0xffffffffu, m, o));
        float e[4], sum = 0.f;
#pragma unroll
        for (int cc = 0; cc < 4; cc++) {
            int j = l + 32 * cc;
            e[cc] = (j < nj) ? expf(v[cc] - m) : 0.f;
            sum += e[cc];
        }
#pragma unroll
        for (int o = 16; o; o >>= 1) sum += __shfl_xor_sync(0xffffffffu, sum, o);
        float inv = 1.f / sum;
#pragma unroll
        for (int cc = 0; cc < 4; cc++) {
            int j = l + 32 * cc;
            if (j < nj) w_s[w * 128 + j] = e[cc] * inv;
        }
    }
    __syncthreads();

    // ---- pass 2: z[bl][h][e] = sum_j w * s ; thread = (bl, 4 e's) ----
    {
        int bl = tid >> 8;
        int e0 = (tid & 255) << 2;
        int b = bb * 2 + bl;
        float za[8][4];
#pragma unroll
        for (int h = 0; h < 8; h++)
#pragma unroll
            for (int u = 0; u < 4; u++) za[h][u] = 0.f;
        for (int j = 0; j < nj; j++) {
            float4 sv = *reinterpret_cast<const float4*>(g_S + (size_t)(j * cB + b) * cE + e0);
#pragma unroll
            for (int h = 0; h < 8; h++) {
                float wj = w_s[(bl * 8 + h) * 128 + j];
                za[h][0] = fmaf(wj, sv.x, za[h][0]);
                za[h][1] = fmaf(wj, sv.y, za[h][1]);
                za[h][2] = fmaf(wj, sv.z, za[h][2]);
                za[h][3] = fmaf(wj, sv.w, za[h][3]);
            }
        }
#pragma unroll
        for (int h = 0; h < 8; h++)
            *reinterpret_cast<float4*>(zs + bl * 8192 + h * 1024 + e0) =
                make_float4(za[h][0], za[h][1], za[h][2], za[h][3]);
    }
    __syncthreads();

    // ---- pass 3: ctx[bl][c] = sum_e z[bl][h(c)][e] Wv[e][c] + bv[c] ----
    {
        int bl = tid >> 8;
        int c2 = (tid & 255) << 1;
        int h = c2 >> 6;
        const float* zrow = zs + bl * 8192 + h * 1024;
        const float* Wv = g_ptr.w[13];
        float a0 = 0.f, a1 = 0.f;
        for (int e = 0; e < 1024; e++) {
            float zv = zrow[e];
            float2 wv = *reinterpret_cast<const float2*>(Wv + (size_t)e * 512 + c2);
            a0 = fmaf(zv, wv.x, a0); a1 = fmaf(zv, wv.y, a1);
        }
        float2 bv2 = *reinterpret_cast<const float2*>(g_ptr.w[14] + c2);
        __syncthreads();   // w_s reads (pass2) complete before overwrite
        *reinterpret_cast<float2*>(w_s + bl * 512 + c2) = make_float2(a0 + bv2.x, a1 + bv2.y);
    }
    __syncthreads();

    // ---- pass 4: X[b, E+e'] = sum_c ctx[bl][c] Wo[c][e'] + bo[e'] ----
    {
        int bl = tid >> 8;
        int e0 = (tid & 255) << 2;
        const float* Wo = g_ptr.w[15];
        float a0 = 0.f, a1 = 0.f, a2 = 0.f, a3 = 0.f;
        for (int c = 0; c < 512; c++) {
            float cv = w_s[bl * 512 + c];
            float4 wo = *reinterpret_cast<const float4*>(Wo + (size_t)c * 1024 + e0);
            a0 = fmaf(cv, wo.x, a0); a1 = fmaf(cv, wo.y, a1);
            a2 = fmaf(cv, wo.z, a2); a3 = fmaf(cv, wo.w, a3);
        }
        float4 bo4 = *reinterpret_cast<const float4*>(g_ptr.w[16] + e0);
        *reinterpret_cast<float4*>(g_X + (bb * 2 + bl) * 2048 + 1024 + e0) =
            make_float4(a0 + bo4.x, a1 + bo4.y, a2 + bo4.z, a3 + bo4.w);
    }
}

// ---------------- final output (B,T,E): step-127 noise ----------------
__global__ __launch_bounds__(256) void k_genout(float* __restrict__ out) {
    int b = blockIdx.x & 127;
    int j = blockIdx.x >> 7;
    int e = threadIdx.x << 2;
    uint2 kk = step_key(cT - 1);
    size_t off = (size_t)(j * cB + b) * cE + e;
    float4 mu = *reinterpret_cast<const float4*>(g_MUS + off);
    float4 sg = *reinterpret_cast<const float4*>(g_SIGS + off);
    unsigned p = (unsigned)((b * cT + j) * cE + e);
    float4 s;
    s.x = fmaf(eps_at(kk.x, kk.y, p + 0), sg.x, mu.x);
    s.y = fmaf(eps_at(kk.x, kk.y, p + 1), sg.y, mu.y);
    s.z = fmaf(eps_at(kk.x, kk.y, p + 2), sg.z, mu.z);
    s.w = fmaf(eps_at(kk.x, kk.y, p + 3), sg.w, mu.w);
    *reinterpret_cast<float4*>(out + p) = s;
}

// ---------------- host side ----------------
extern "C" void kernel_launch(void* const* d_in, const int* in_sizes, int n_in,
                              void* d_out, int out_size) {
    Ptrs P;
    for (int k = 0; k < 17; k++) P.w[k] = (const float*)d_in[k];
    float* out = (float*)d_out;

    constexpr int ATTN_SMEM = (16384 + 2048 + 8192) * 4;   // 106496 B
    cudaFuncSetAttribute(k_attn, cudaFuncAttributeMaxDynamicSharedMemorySize, ATTN_SMEM);

    k_setup<<<1, 1>>>(P);
    k_init<<<6144, 256>>>();
    k_gemm<<<dim3(1, 24, 1), 256>>>(SEL_EB, 0);      // encs half of gi (once)

    for (int i = 0; i < cT; i++) {
        k_gemm<<<dim3(1, 24, 8), 256>>>(SEL_GIC, i); // ctx-half gi, ksplit8
        k_combine<<<512, 256>>>();                   // h update (uses prev GH4)
        k_gemm<<<dim3(1, 40, 4), 256>>>(SEL_HMS, i); // h@[W_hh|W_mu|W_sig]

        if (i < cT - 1) {
            k_gen_s<<<(i + 1) * cB, 256>>>(i);       // finalize mu/sig row i + sample S
            k_gemm<<<dim3(1, 4, 8), 256>>>(SEL_QB, i);   // q partials, ksplit8
            k_gemm<<<dim3(1, 8, 8), 256>>>(SEL_UB, i);   // u per head (sums q)
            k_attn<<<64, 512, ATTN_SMEM>>>(i);
        } else {
            k_msfix<<<cB, 256>>>(i);
        }
    }

    k_genout<<<cT * cB, 256>>>(out);
}

// round 11
// speedup vs baseline: 3.0758x; 1.0445x over previous
#include <cuda_runtime.h>
#include <cstdint>
#include <cmath>

// ---------------- problem constants ----------------
constexpr int cB = 128, cT = 128, cE = 1024, cH = 1024, cNH = 8, cA = 64;
constexpr int cKV = cNH * cA;          // 512
constexpr int BE  = cB * cE;           // 131072

// ---------------- persistent device scratch ----------------
__device__ float g_MUS [cT * BE];          // (T,B,E)
__device__ float g_SIGS[cT * BE];          // (T,B,E)
__device__ float g_S   [cT * BE];          // (T,B,E)
__device__ float g_X   [cB * 2048];        // [encs | context]
__device__ float g_H   [cB * cH];
__device__ float g_GIE [cB * 3072];        // encs @ W_ih[:, :E]^T (once)
__device__ float g_GI8 [8][cB * 3072];     // ctx-half gi partials (ksplit8)
__device__ float g_GH4 [4][cB * 3072];     // gh partials (ksplit4)
__device__ float g_MSP [8][cB * cE];       // mu partials [0..3], sig partials [4..7]
__device__ float g_QP  [4][cB * cKV];      // q partials (ksplit4)
__device__ float g_U   [cB * cNH * cE];    // (b,h,e)

struct Ptrs { const float* w[17]; };
__device__ Ptrs g_ptr;

// ---------------- threefry2x32 (jax-exact bits) ----------------
__device__ __forceinline__ uint2 tf2x32(unsigned k0, unsigned k1, unsigned x0, unsigned x1) {
    unsigned k2 = k0 ^ k1 ^ 0x1BD11BDAu;
    x0 += k0; x1 += k1;
#define TFR(r) x0 += x1; x1 = __funnelshift_l(x1, x1, r); x1 ^= x0;
    TFR(13) TFR(15) TFR(26) TFR(6)   x0 += k1; x1 += k2 + 1u;
    TFR(17) TFR(29) TFR(16) TFR(24)  x0 += k2; x1 += k0 + 2u;
    TFR(13) TFR(15) TFR(26) TFR(6)   x0 += k0; x1 += k1 + 3u;
    TFR(17) TFR(29) TFR(16) TFR(24)  x0 += k1; x1 += k2 + 4u;
    TFR(13) TFR(15) TFR(26) TFR(6)   x0 += k2; x1 += k0 + 5u;
#undef TFR
    return make_uint2(x0, x1);
}
__device__ __forceinline__ uint2 step_key(int i) { return tf2x32(0u, 1234u, 0u, (unsigned)i); }

// bits -> N(0,1): jax _uniform + sqrt(2)*erf_inv (Giles poly), fast-log variant.
// |eps error| ~2e-7 relative: irrelevant vs 1e-3 output tolerance.
__device__ __forceinline__ float tf_normal(unsigned bits) {
    float f = __uint_as_float((bits >> 9) | 0x3f800000u) - 1.0f;
    float u = fmaf(f, 2.0f, -0.99999994f);
    u = fmaxf(u, -0.99999994f);
    float w = -__logf(fmaf(-u, u, 1.0f));
    float p;
    if (w < 5.0f) {
        w -= 2.5f;
        p = 2.81022636e-08f;
        p = fmaf(p, w, 3.43273939e-07f);
        p = fmaf(p, w, -3.5233877e-06f);
        p = fmaf(p, w, -4.39150654e-06f);
        p = fmaf(p, w, 0.00021858087f);
        p = fmaf(p, w, -0.00125372503f);
        p = fmaf(p, w, -0.00417768164f);
        p = fmaf(p, w, 0.246640727f);
        p = fmaf(p, w, 1.50140941f);
    } else {
        w = sqrtf(w) - 3.0f;
        p = -0.000200214257f;
        p = fmaf(p, w, 0.000100950558f);
        p = fmaf(p, w, 0.00134934322f);
        p = fmaf(p, w, -0.00367342844f);
        p = fmaf(p, w, 0.00573950773f);
        p = fmaf(p, w, -0.0076224613f);
        p = fmaf(p, w, 0.00943887047f);
        p = fmaf(p, w, 1.00167406f);
        p = fmaf(p, w, 2.83297682f);
    }
    return 1.4142135623730951f * (p * u);
}
__device__ __forceinline__ float eps_at(unsigned k0, unsigned k1, unsigned idx) {
    uint2 r = tf2x32(k0, k1, 0u, idx);
    return tf_normal(r.x ^ r.y);
}
__device__ __forceinline__ float softplusf(float x) {
    return fmaxf(x, 0.f) + log1pf(expf(-fabsf(x)));
}

// ---------------- setup + init ----------------
__global__ void k_setup(Ptrs p) { g_ptr = p; }
__global__ void k_init() {
    int idx = blockIdx.x * 256 + threadIdx.x;
    const float* encs = g_ptr.w[0];
    if (idx < cB * 2048) {
        int b = idx >> 11, c = idx & 2047;
        g_X[idx] = (c < cE) ? encs[b * cE + c] : 0.f;
    }
    if (idx < cB * cH) g_H[idx] = 0.f;
    if (idx < 4 * cB * 3072) reinterpret_cast<float*>(g_GH4)[idx] = 0.f;  // h0=0 -> gh=0
}

// ---- SGEMM (R9 measured-best): BM=128, BN=64, BK=8, 128 thr, 8x8, dbl-buf --
enum { SEL_EB = 0, SEL_GIC, SEL_HMS, SEL_QB, SEL_UB };

struct GD {
    const float* A; const float* Bm; float* C; const float* qbias;
    int lda, ldb, ldc, K, transB, qsum;
};

__device__ __forceinline__ GD get_desc(int sel, int y, int z, int i) {
    GD d; d.qbias = nullptr; d.transB = 0; d.qsum = 0;
    switch (sel) {
    case SEL_EB:   // encs @ W_ih[:, :E]^T ; y in [0,48)
        d.A = g_ptr.w[0]; d.lda = 1024; d.K = 1024;
        d.Bm = g_ptr.w[1] + (size_t)(y * 64) * 2048; d.ldb = 2048; d.transB = 1;
        d.C = g_GIE + y * 64; d.ldc = 3072; break;
    case SEL_GIC:  // ctx @ W_ih[:, E:]^T ; ksplit8 (z), y in [0,48)
        d.A = g_X + 1024 + z * 128; d.lda = 2048; d.K = 128;
        d.Bm = g_ptr.w[1] + 1024 + z * 128 + (size_t)(y * 64) * 2048; d.ldb = 2048; d.transB = 1;
        d.C = g_GI8[z] + y * 64; d.ldc = 3072; break;
    case SEL_HMS:  // h @ [W_hh^T | W_mu | W_sig] ; ksplit4 (z), y in [0,80)
        d.A = g_H + z * 256; d.lda = 1024; d.K = 256;
        if (y < 48) {
            d.Bm = g_ptr.w[2] + z * 256 + (size_t)(y * 64) * 1024; d.ldb = 1024; d.transB = 1;
            d.C = g_GH4[z] + y * 64; d.ldc = 3072;
        } else if (y < 64) {
            int yy = y - 48;
            d.Bm = g_ptr.w[5] + (size_t)(z * 256) * 1024 + yy * 64; d.ldb = 1024;
            d.C = g_MSP[z] + yy * 64; d.ldc = 1024;
        } else {
            int yy = y - 64;
            d.Bm = g_ptr.w[7] + (size_t)(z * 256) * 1024 + yy * 64; d.ldb = 1024;
            d.C = g_MSP[4 + z] + yy * 64; d.ldc = 1024;
        }
        break;
    case SEL_QB:   // s_i @ W_q ; ksplit4 (z), y in [0,8)
        d.A = g_S + (size_t)i * BE + z * 256; d.lda = 1024; d.K = 256;
        d.Bm = g_ptr.w[9] + (size_t)(z * 256) * 512 + y * 64; d.ldb = 512;
        d.C = g_QP[z] + y * 64; d.ldc = 512; break;
    default:       // SEL_UB: u_h = (sum q-partials + b_q) @ W_k_h^T ; z=head, y in [0,16)
        d.qsum = 1;
        d.A = g_QP[0] + z * 64; d.lda = 512; d.K = 64;
        d.qbias = g_ptr.w[10] + z * 64;
        d.Bm = g_ptr.w[11] + z * 64 + (size_t)(y * 64) * 512; d.ldb = 512; d.transB = 1;
        d.C = g_U + z * 1024 + y * 64; d.ldc = 8192; break;
    }
    return d;
}

__global__ __launch_bounds__(128) void k_gemm(int sel, int i) {
    GD d = get_desc(sel, blockIdx.y, blockIdx.z, i);

    __shared__ __align__(16) float As[2][8][132];
    __shared__ __align__(16) float Bs[2][8][68];

    int tid = threadIdx.x;
    int tx = tid & 7, ty = tid >> 3;

    float acc[8][8];
#pragma unroll
    for (int r = 0; r < 8; r++)
#pragma unroll
        for (int c = 0; c < 8; c++) acc[r][c] = 0.f;

    float4 va[2]; float4 vb;
    int arow = tid >> 1, akc = (tid & 1) << 2;
    int bkk = tid >> 4, bnc = (tid & 15) << 2;
    int bnn = tid >> 1, bkc = (tid & 1) << 2;

    auto loadT = [&](int k0) {
#pragma unroll
        for (int r = 0; r < 2; r++) {
            const float* ap = d.A + (size_t)(arow + r * 64) * d.lda + k0 + akc;
            if (!d.qsum) {
                va[r] = *reinterpret_cast<const float4*>(ap);
            } else {
                float4 v0 = *reinterpret_cast<const float4*>(ap);
                float4 v1 = *reinterpret_cast<const float4*>(ap + 65536);
                float4 v2 = *reinterpret_cast<const float4*>(ap + 131072);
                float4 v3 = *reinterpret_cast<const float4*>(ap + 196608);
                float4 bb = *reinterpret_cast<const float4*>(d.qbias + k0 + akc);
                va[r].x = v0.x + v1.x + v2.x + v3.x + bb.x;
                va[r].y = v0.y + v1.y + v2.y + v3.y + bb.y;
                va[r].z = v0.z + v1.z + v2.z + v3.z + bb.z;
                va[r].w = v0.w + v1.w + v2.w + v3.w + bb.w;
            }
        }
        if (!d.transB)
            vb = *reinterpret_cast<const float4*>(d.Bm + (size_t)(k0 + bkk) * d.ldb + bnc);
        else
            vb = *reinterpret_cast<const float4*>(d.Bm + (size_t)bnn * d.ldb + k0 + bkc);
    };
    auto storeT = [&](int cur) {
#pragma unroll
        for (int r = 0; r < 2; r++) {
            int row = arow + r * 64;
            As[cur][akc + 0][row] = va[r].x; As[cur][akc + 1][row] = va[r].y;
            As[cur][akc + 2][row] = va[r].z; As[cur][akc + 3][row] = va[r].w;
        }
        if (!d.transB) {
            *reinterpret_cast<float4*>(&Bs[cur][bkk][bnc]) = vb;
        } else {
            Bs[cur][bkc + 0][bnn] = vb.x; Bs[cur][bkc + 1][bnn] = vb.y;
            Bs[cur][bkc + 2][bnn] = vb.z; Bs[cur][bkc + 3][bnn] = vb.w;
        }
    };

    int nt = d.K >> 3;
    loadT(0);
    int cur = 0;
    for (int t = 0; t < nt; t++) {
        storeT(cur);
        __syncthreads();
        if (t + 1 < nt) loadT((t + 1) << 3);
#pragma unroll
        for (int kk = 0; kk < 8; kk++) {
            float4 a0 = *reinterpret_cast<const float4*>(&As[cur][kk][ty * 8]);
            float4 a1 = *reinterpret_cast<const float4*>(&As[cur][kk][ty * 8 + 4]);
            float4 b0 = *reinterpret_cast<const float4*>(&Bs[cur][kk][tx * 8]);
            float4 b1 = *reinterpret_cast<const float4*>(&Bs[cur][kk][tx * 8 + 4]);
            float af[8] = {a0.x, a0.y, a0.z, a0.w, a1.x, a1.y, a1.z, a1.w};
            float bf[8] = {b0.x, b0.y, b0.z, b0.w, b1.x, b1.y, b1.z, b1.w};
#pragma unroll
            for (int r = 0; r < 8; r++)
#pragma unroll
                for (int c = 0; c < 8; c++) acc[r][c] = fmaf(af[r], bf[c], acc[r][c]);
        }
        cur ^= 1;
    }

#pragma unroll
    for (int r = 0; r < 8; r++) {
        int m = ty * 8 + r;
        float* cp = d.C + (size_t)m * d.ldc + tx * 8;
        *reinterpret_cast<float4*>(cp)     = make_float4(acc[r][0], acc[r][1], acc[r][2], acc[r][3]);
        *reinterpret_cast<float4*>(cp + 4) = make_float4(acc[r][4], acc[r][5], acc[r][6], acc[r][7]);
    }
}

// ---------------- GRU gate combine (sums GI8 x8 + GH4 x4 partials) ---------
__global__ void k_combine() {
    int idx = blockIdx.x * 256 + threadIdx.x;
    int b = idx >> 10, m = idx & 1023;
    const float* b_ih = g_ptr.w[3];
    const float* b_hh = g_ptr.w[4];
    int o = b * 3072;
    float ir = g_GIE[o + m] + b_ih[m];
    float iz = g_GIE[o + m + 1024] + b_ih[m + 1024];
    float in = g_GIE[o + m + 2048] + b_ih[m + 2048];
#pragma unroll
    for (int p = 0; p < 8; p++) {
        ir += g_GI8[p][o + m];
        iz += g_GI8[p][o + m + 1024];
        in += g_GI8[p][o + m + 2048];
    }
    float hr = b_hh[m], hz = b_hh[m + 1024], hn = b_hh[m + 2048];
#pragma unroll
    for (int p = 0; p < 4; p++) {
        hr += g_GH4[p][o + m];
        hz += g_GH4[p][o + m + 1024];
        hn += g_GH4[p][o + m + 2048];
    }
    float r = 1.f / (1.f + expf(-(ir + hr)));
    float z = 1.f / (1.f + expf(-(iz + hz)));
    float n = tanhf(fmaf(r, hn, in));
    float h = g_H[idx];
    g_H[idx] = fmaf(z, h - n, n);
}

// ---- gen_s: finalize row i + sample; 8 elems/thread for threefry ILP ------
// grid = (i+1)*64 blocks, 256 thr; block covers row j for b-pair.
__global__ __launch_bounds__(256) void k_gen_s(int i) {
    int j  = blockIdx.x >> 6;
    int b  = ((blockIdx.x & 63) << 1) + (threadIdx.x >> 7);
    int e  = (threadIdx.x & 127) << 3;
    uint2 kk = step_key(i);
    size_t off = (size_t)(j * cB + b) * cE + e;
    float4 mu0, mu1, sg0, sg1;
    if (j == i) {
        int q = b * 1024 + e;
        mu0 = *reinterpret_cast<const float4*>(g_ptr.w[6] + e);
        mu1 = *reinterpret_cast<const float4*>(g_ptr.w[6] + e + 4);
        sg0 = *reinterpret_cast<const float4*>(g_ptr.w[8] + e);
        sg1 = *reinterpret_cast<const float4*>(g_ptr.w[8] + e + 4);
#pragma unroll
        for (int p = 0; p < 4; p++) {
            float4 m0 = *reinterpret_cast<const float4*>(&g_MSP[p][q]);
            float4 m1 = *reinterpret_cast<const float4*>(&g_MSP[p][q + 4]);
            float4 s0 = *reinterpret_cast<const float4*>(&g_MSP[p + 4][q]);
            float4 s1 = *reinterpret_cast<const float4*>(&g_MSP[p + 4][q + 4]);
            mu0.x += m0.x; mu0.y += m0.y; mu0.z += m0.z; mu0.w += m0.w;
            mu1.x += m1.x; mu1.y += m1.y; mu1.z += m1.z; mu1.w += m1.w;
            sg0.x += s0.x; sg0.y += s0.y; sg0.z += s0.z; sg0.w += s0.w;
            sg1.x += s1.x; sg1.y += s1.y; sg1.z += s1.z; sg1.w += s1.w;
        }
        sg0.x = softplusf(sg0.x); sg0.y = softplusf(sg0.y);
        sg0.z = softplusf(sg0.z); sg0.w = softplusf(sg0.w);
        sg1.x = softplusf(sg1.x); sg1.y = softplusf(sg1.y);
        sg1.z = softplusf(sg1.z); sg1.w = softplusf(sg1.w);
        *reinterpret_cast<float4*>(g_MUS + off) = mu0;
        *reinterpret_cast<float4*>(g_MUS + off + 4) = mu1;
        *reinterpret_cast<float4*>(g_SIGS + off) = sg0;
        *reinterpret_cast<float4*>(g_SIGS + off + 4) = sg1;
    } else {
        mu0 = *reinterpret_cast<const float4*>(g_MUS + off);
        mu1 = *reinterpret_cast<const float4*>(g_MUS + off + 4);
        sg0 = *reinterpret_cast<const float4*>(g_SIGS + off);
        sg1 = *reinterpret_cast<const float4*>(g_SIGS + off + 4);
    }
    unsigned p = (unsigned)((b * cT + j) * cE + e);
    float ep[8];
#pragma unroll
    for (int u = 0; u < 8; u++) ep[u] = eps_at(kk.x, kk.y, p + u);
    float4 s0, s1;
    s0.x = fmaf(ep[0], sg0.x, mu0.x); s0.y = fmaf(ep[1], sg0.y, mu0.y);
    s0.z = fmaf(ep[2], sg0.z, mu0.z); s0.w = fmaf(ep[3], sg0.w, mu0.w);
    s1.x = fmaf(ep[4], sg1.x, mu1.x); s1.y = fmaf(ep[5], sg1.y, mu1.y);
    s1.z = fmaf(ep[6], sg1.z, mu1.z); s1.w = fmaf(ep[7], sg1.w, mu1.w);
    *reinterpret_cast<float4*>(g_S + off) = s0;
    *reinterpret_cast<float4*>(g_S + off + 4) = s1;
}

// finalize-only (step 127)
__global__ __launch_bounds__(256) void k_msfix(int i) {
    int b = blockIdx.x;
    int e = threadIdx.x << 2;
    int q = b * 1024 + e;
    size_t off = (size_t)(i * cB + b) * cE + e;
    float4 mu = *reinterpret_cast<const float4*>(g_ptr.w[6] + e);
    float4 sg = *reinterpret_cast<const float4*>(g_ptr.w[8] + e);
#pragma unroll
    for (int p = 0; p < 4; p++) {
        float4 mp = *reinterpret_cast<const float4*>(&g_MSP[p][q]);
        float4 sp = *reinterpret_cast<const float4*>(&g_MSP[p + 4][q]);
        mu.x += mp.x; mu.y += mp.y; mu.z += mp.z; mu.w += mp.w;
        sg.x += sp.x; sg.y += sp.y; sg.z += sp.z; sg.w += sp.w;
    }
    sg.x = softplusf(sg.x); sg.y = softplusf(sg.y);
    sg.z = softplusf(sg.z); sg.w = softplusf(sg.w);
    *reinterpret_cast<float4*>(g_MUS + off) = mu;
    *reinterpret_cast<float4*>(g_SIGS + off) = sg;
}

// ---------------- mega attention: 2 b's per block, 64 blocks, 512 threads ---
// smem: z[16384] + w_s[2048] + s_st[8192] (4 j-rows x 2 b staged per round)
__global__ __launch_bounds__(512) void k_attn(int i) {
    extern __shared__ float sm[];
    float* zs  = sm;            // 16384 floats (z, pass2+)
    float* w_s = sm + 16384;    // 2048 floats
    float* s_st = sm + 18432;   // 8192 floats: [bl][jr][1024]
    int bb = blockIdx.x;
    int nj = i + 1;
    int tid = threadIdx.x;
    int w = tid >> 5, l = tid & 31;
    int blw = w >> 3, hw = w & 7;

    // ---- pass 1: scores; u held in registers, 4 j-rows staged per round ----
    {
        float4 ureg[8];
        const float4* up = reinterpret_cast<const float4*>(
            g_U + (size_t)(bb * 2 + blw) * 8192 + hw * 1024);
#pragma unroll
        for (int k = 0; k < 8; k++) ureg[k] = up[l + 32 * k];

        for (int j0 = 0; j0 < nj; j0 += 4) {
#pragma unroll
            for (int r = 0; r < 4; r++) {
                int idx = tid + r * 512;
                int row = idx >> 8;
                int bl = row >> 2, jr = row & 3;
                int j = j0 + jr;
                if (j < nj)
                    reinterpret_cast<float4*>(s_st)[idx] =
                        reinterpret_cast<const float4*>(
                            g_S + (size_t)(j * cB + bb * 2 + bl) * cE)[idx & 255];
            }
            __syncthreads();
            const float4* sbase = reinterpret_cast<const float4*>(s_st + blw * 4096);
#pragma unroll
            for (int jr = 0; jr < 4; jr++) {
                int j = j0 + jr;
                if (j < nj) {
                    const float4* sv4 = sbase + jr * 256;
                    float acc = 0.f;
#pragma unroll
                    for (int k = 0; k < 8; k++) {
                        float4 sv = sv4[l + 32 * k];
                        acc = fmaf(sv.x, ureg[k].x, acc); acc = fmaf(sv.y, ureg[k].y, acc);
                        acc = fmaf(sv.z, ureg[k].z, acc); acc = fmaf(sv.w, ureg[k].w, acc);
                    }
#pragma unroll
                    for (int o = 16; o; o >>= 1) acc += __shfl_xor_sync(0xffffffffu, acc, o);
                    if (l == 0) w_s[w * 128 + j] = acc * 0.125f;   // 1/sqrt(64)
                }
            }
            __syncthreads();
        }
    }

    // ---- softmax per (bl,h) combo = warp ----
    {
        float v[4];
#pragma unroll
        for (int cc = 0; cc < 4; cc++) {
            int j = l + 32 * cc;
            v[cc] = (j < nj) ? w_s[w * 128 + j] : -3.0e38f;
        }
        float m = fmaxf(fmaxf(v[0], v[1]), fmaxf(v[2], v[3]));
#pragma unroll
        for (int o = 16; o; o >>= 1) m = fmaxf(m, __shfl_xor_sync(0xffffffffu, m, o));
        float e[4], sum = 0.f;
#pragma unroll
        for (int cc = 0; cc < 4; cc++) {
            int j = l + 32 * cc;
            e[cc] = (j < nj) ? expf(v[cc] - m) : 0.f;
            sum += e[cc];
        }
#pragma unroll
        for (int o = 16; o; o >>= 1) sum += __shfl_xor_sync(0xffffffffu, sum, o);
        float inv = 1.f / sum;
#pragma unroll
        for (int cc = 0; cc < 4; cc++) {
            int j = l + 32 * cc;
            if (j < nj) w_s[w * 128 + j] = e[cc] * inv;
        }
    }
    __syncthreads();

    // ---- pass 2: z[bl][h][e] = sum_j w * s ----
    {
        int bl = tid >> 8;
        int e0 = (tid & 255) << 2;
        int b = bb * 2 + bl;
        float za[8][4];
#pragma unroll
        for (int h = 0; h < 8; h++)
#pragma unroll
            for (int u = 0; u < 4; u++) za[h][u] = 0.f;
        for (int j = 0; j < nj; j++) {
            float4 sv = *reinterpret_cast<const float4*>(g_S + (size_t)(j * cB + b) * cE + e0);
#pragma unroll
            for (int h = 0; h < 8; h++) {
                float wj = w_s[(bl * 8 + h) * 128 + j];
                za[h][0] = fmaf(wj, sv.x, za[h][0]);
                za[h][1] = fmaf(wj, sv.y, za[h][1]);
                za[h][2] = fmaf(wj, sv.z, za[h][2]);
                za[h][3] = fmaf(wj, sv.w, za[h][3]);
            }
        }
#pragma unroll
        for (int h = 0; h < 8; h++)
            *reinterpret_cast<float4*>(zs + bl * 8192 + h * 1024 + e0) =
                make_float4(za[h][0], za[h][1], za[h][2], za[h][3]);
    }
    __syncthreads();

    // ---- pass 3: ctx ----
    {
        int bl = tid >> 8;
        int c2 = (tid & 255) << 1;
        int h = c2 >> 6;
        const float* zrow = zs + bl * 8192 + h * 1024;
        const float* Wv = g_ptr.w[13];
        float a0 = 0.f, a1 = 0.f;
        for (int e = 0; e < 1024; e++) {
            float zv = zrow[e];
            float2 wv = *reinterpret_cast<const float2*>(Wv + (size_t)e * 512 + c2);
            a0 = fmaf(zv, wv.x, a0); a1 = fmaf(zv, wv.y, a1);
        }
        float2 bv2 = *reinterpret_cast<const float2*>(g_ptr.w[14] + c2);
        __syncthreads();
        *reinterpret_cast<float2*>(w_s + bl * 512 + c2) = make_float2(a0 + bv2.x, a1 + bv2.y);
    }
    __syncthreads();

    // ---- pass 4: out-proj into X ----
    {
        int bl = tid >> 8;
        int e0 = (tid & 255) << 2;
        const float* Wo = g_ptr.w[15];
        float a0 = 0.f, a1 = 0.f, a2 = 0.f, a3 = 0.f;
        for (int c = 0; c < 512; c++) {
            float cv = w_s[bl * 512 + c];
            float4 wo = *reinterpret_cast<const float4*>(Wo + (size_t)c * 1024 + e0);
            a0 = fmaf(cv, wo.x, a0); a1 = fmaf(cv, wo.y, a1);
            a2 = fmaf(cv, wo.z, a2); a3 = fmaf(cv, wo.w, a3);
        }
        float4 bo4 = *reinterpret_cast<const float4*>(g_ptr.w[16] + e0);
        *reinterpret_cast<float4*>(g_X + (bb * 2 + bl) * 2048 + 1024 + e0) =
            make_float4(a0 + bo4.x, a1 + bo4.y, a2 + bo4.z, a3 + bo4.w);
    }
}

// ---------------- final output (B,T,E): step-127 noise, 8 elems/thread -----
__global__ __launch_bounds__(256) void k_genout(float* __restrict__ out) {
    int j = blockIdx.x >> 6;
    int b = ((blockIdx.x & 63) << 1) + (threadIdx.x >> 7);
    int e = (threadIdx.x & 127) << 3;
    uint2 kk = step_key(cT - 1);
    size_t off = (size_t)(j * cB + b) * cE + e;
    float4 mu0 = *reinterpret_cast<const float4*>(g_MUS + off);
    float4 mu1 = *reinterpret_cast<const float4*>(g_MUS + off + 4);
    float4 sg0 = *reinterpret_cast<const float4*>(g_SIGS + off);
    float4 sg1 = *reinterpret_cast<const float4*>(g_SIGS + off + 4);
    unsigned p = (unsigned)((b * cT + j) * cE + e);
    float ep[8];
#pragma unroll
    for (int u = 0; u < 8; u++) ep[u] = eps_at(kk.x, kk.y, p + u);
    float4 s0, s1;
    s0.x = fmaf(ep[0], sg0.x, mu0.x); s0.y = fmaf(ep[1], sg0.y, mu0.y);
    s0.z = fmaf(ep[2], sg0.z, mu0.z); s0.w = fmaf(ep[3], sg0.w, mu0.w);
    s1.x = fmaf(ep[4], sg1.x, mu1.x); s1.y = fmaf(ep[5], sg1.y, mu1.y);
    s1.z = fmaf(ep[6], sg1.z, mu1.z); s1.w = fmaf(ep[7], sg1.w, mu1.w);
    *reinterpret_cast<float4*>(out + p) = s0;
    *reinterpret_cast<float4*>(out + p + 4) = s1;
}

// ---------------- host side ----------------
extern "C" void kernel_launch(void* const* d_in, const int* in_sizes, int n_in,
                              void* d_out, int out_size) {
    Ptrs P;
    for (int k = 0; k < 17; k++) P.w[k] = (const float*)d_in[k];
    float* out = (float*)d_out;

    constexpr int ATTN_SMEM = (16384 + 2048 + 8192) * 4;   // 106496 B
    cudaFuncSetAttribute(k_attn, cudaFuncAttributeMaxDynamicSharedMemorySize, ATTN_SMEM);

    k_setup<<<1, 1>>>(P);
    k_init<<<6144, 256>>>();
    k_gemm<<<dim3(1, 48, 1), 128>>>(SEL_EB, 0);      // encs half of gi (once)

    for (int i = 0; i < cT; i++) {
        k_gemm<<<dim3(1, 48, 8), 128>>>(SEL_GIC, i); // ctx-half gi, ksplit8
        k_combine<<<512, 256>>>();                   // h update (uses prev GH4)
        k_gemm<<<dim3(1, 80, 4), 128>>>(SEL_HMS, i); // h@[W_hh|W_mu|W_sig]

        if (i < cT - 1) {
            k_gen_s<<<(i + 1) * 64, 256>>>(i);       // finalize mu/sig row i + sample S
            k_gemm<<<dim3(1, 8, 4), 128>>>(SEL_QB, i);
            k_gemm<<<dim3(1, 16, 8), 128>>>(SEL_UB, i);
            k_attn<<<64, 512, ATTN_SMEM>>>(i);
        } else {
            k_msfix<<<cB, 256>>>(i);
        }
    }

    k_genout<<<cT * 64, 256>>>(out);
}